// round 9
// baseline (speedup 1.0000x reference)
#include <cuda_runtime.h>

// OrbitalSpectralConv: B=8, C=128, H=W=128; kept modes: 32 kx rows x 17 ky cols.
// kx rows: mk 0..16 -> kx = mk; mk 17..31 -> kx = mk+96 == -(32-mk) mod 128.
#define NKY   17
#define NMODE 544           // 32*17
#define NSLICE 1024         // B*C

// Scratch (allocation banned -> device globals).
__device__ float2 g_Xf[128 * NMODE * 8];         // 4.45 MB  [c][m][b]
__device__ float2 g_Y [NSLICE * NMODE];          // 4.45 MB  [b][c][m]

// ===========================================================================
// Fused forward: per (b,c) slice.
// Phase A (w-DFT, folded): G[h][ky] = Sp[h][0] + (-1)^ky Sp[h][64]
//     + sum_{w=1..63} Sp[h][w] cos(t ky w) - i Sm[h][w] sin(t ky w)
//   Sp[w]=x[w]+x[128-w], Sm[w]=x[w]-x[128-w], t=2pi/128.  -> Gs in smem.
// Phase B (h-DFT, folded, rotation trig):
//   C1=sum cos(ah) Gp_re, C2=sum cos(ah) Gp_im, S1=sum sin(ah) Gm_re, S2=..im
//   Xf[+a]=(C1+S2, C2-S1), Xf[-a]=(C1-S2, C2+S1), scaled 1/16384,
//   written to g_Xf in [c][m][b] layout.
// 320 threads; phase A: 5 ky-groups of 4 (group 4 computes ky16 + 3 discarded).
// ===========================================================================
__global__ __launch_bounds__(320) void k_fwd(const float* __restrict__ X) {
    extern __shared__ char smraw[];
    float2* T1 = (float2*)smraw;                 // [64][18] + 4 pad
    float*  Sp = (float*)(T1 + 64 * 18 + 4);     // [64][65]
    float*  Sm = Sp + 64 * 65;                   // [64][65]
    float2* Gs = (float2*)(Sm + 64 * 65);        // [128][17]

    const int tid = threadIdx.x;

    // trig rows: T1[w][ky] = (cos,sin)(2pi w ky/128); init all 18 cols + pad.
    for (int i = tid; i < 64 * 18 + 4; i += 320) {
        int w = i / 18, ky = i - w * 18;
        float s, c;
        sincospif((float)((w * ky) & 127) * (2.0f / 128.0f), &s, &c);
        T1[i] = make_float2(c, s);
    }

    const float* Xp = X + (size_t)blockIdx.x * 16384;

    const int hl = tid & 63;
    const int kb = (tid >> 6) << 2;   // 0,4,8,12,16

    for (int half = 0; half < 2; half++) {
        __syncthreads();              // protects T1 (1st iter) and Sp/Sm reuse
        for (int i = tid; i < 64 * 64; i += 320) {
            int hr = i >> 6, w = i & 63;
            const float* row = Xp + (half * 64 + hr) * 128;
            float xa = row[w];
            if (w == 0) {
                Sp[hr * 65 + 0]  = xa;
                Sp[hr * 65 + 64] = row[64];
            } else {
                float xb = row[128 - w];
                Sp[hr * 65 + w] = xa + xb;
                Sm[hr * 65 + w] = xa - xb;
            }
        }
        __syncthreads();

        float gre[4], gim[4];
        float s0 = Sp[hl * 65 + 0], s64 = Sp[hl * 65 + 64];
        #pragma unroll
        for (int j = 0; j < 4; j++) {
            gre[j] = s0 + (((kb + j) & 1) ? -s64 : s64);
            gim[j] = 0.f;
        }
        #pragma unroll 7
        for (int w = 1; w < 64; w++) {
            float sp  = Sp[hl * 65 + w];
            float nsm = -Sm[hl * 65 + w];
            const float4* tp = (const float4*)(T1 + w * 18 + kb);
            float4 tA = tp[0];   // ky kb, kb+1
            float4 tB = tp[1];   // ky kb+2, kb+3
            gre[0] = fmaf(tA.x, sp, gre[0]);  gim[0] = fmaf(tA.y, nsm, gim[0]);
            gre[1] = fmaf(tA.z, sp, gre[1]);  gim[1] = fmaf(tA.w, nsm, gim[1]);
            gre[2] = fmaf(tB.x, sp, gre[2]);  gim[2] = fmaf(tB.y, nsm, gim[2]);
            gre[3] = fmaf(tB.z, sp, gre[3]);  gim[3] = fmaf(tB.w, nsm, gim[3]);
        }
        const int h = half * 64 + hl;
        #pragma unroll
        for (int j = 0; j < 4; j++)
            if (kb + j < NKY)
                Gs[h * NKY + kb + j] = make_float2(gre[j], gim[j]);
    }
    __syncthreads();

    // Phase B
    if (tid < 17 * NKY) {
        const int a = tid / NKY, ky = tid - a * NKY;
        float cw, sw;
        sincospif((float)a * (1.0f / 64.0f), &sw, &cw);   // e^{i 2pi a/128}

        float2 g0  = Gs[0 * NKY + ky];
        float2 g64 = Gs[64 * NKY + ky];
        const float sgn = (a & 1) ? -1.f : 1.f;
        float C1 = g0.x + sgn * g64.x;
        float C2 = g0.y + sgn * g64.y;
        float S1 = 0.f, S2 = 0.f;

        float tc = cw, ts = sw;
        #pragma unroll 3
        for (int h = 1; h < 64; h++) {
            float2 ga = Gs[h * NKY + ky];
            float2 gb = Gs[(128 - h) * NKY + ky];
            float pr = ga.x + gb.x, pi = ga.y + gb.y;
            float mr = ga.x - gb.x, mi = ga.y - gb.y;
            C1 = fmaf(tc, pr, C1);
            C2 = fmaf(tc, pi, C2);
            S1 = fmaf(ts, mr, S1);
            S2 = fmaf(ts, mi, S2);
            float nc = fmaf(tc, cw, -ts * sw);
            ts = fmaf(tc, sw,  ts * cw);
            tc = nc;
        }

        const float inv = 1.0f / 16384.0f;
        const int b = blockIdx.x >> 7, c = blockIdx.x & 127;
        float2* Xfb = g_Xf + (size_t)c * (NMODE * 8) + b;
        Xfb[(a * NKY + ky) * 8] = make_float2((C1 + S2) * inv, (C2 - S1) * inv);
        if (a >= 1 && a <= 15)
            Xfb[((32 - a) * NKY + ky) * 8] =
                make_float2((C1 - S2) * inv, (C2 + S1) * inv);
    }
}

// ===========================================================================
// Kernel 2: spectral channel mix, skew-Hermitian weight built on the fly.
//   Y[b,c,m] = sum_ct [(re[c,ct,m]-re[ct,c,m]) + i(im[c,ct,m]+im[ct,c,m])] Xf[b,ct,m]
// grid (17 m-tiles x 16 c-tiles), block 256 = 32 m x 8 c. Thread = (c, m),
// 8 batch complex accumulators; Xf loads are 4x LDG.128 (batches contiguous).
// ===========================================================================
__global__ __launch_bounds__(256) void k_mix(const float* __restrict__ re,
                                             const float* __restrict__ im) {
    const int mi = threadIdx.x & 31;
    const int ci = threadIdx.x >> 5;
    const int m  = blockIdx.x * 32 + mi;
    const int c  = blockIdx.y * 8 + ci;

    float yr[8], yi[8];
    #pragma unroll
    for (int b = 0; b < 8; b++) { yr[b] = 0.f; yi[b] = 0.f; }

    const float* reA = re + (size_t)c * (128 * NMODE) + m;   // [c][ct][m]
    const float* reB = re + (size_t)c * NMODE + m;           // [ct][c][m]
    const float* imA = im + (size_t)c * (128 * NMODE) + m;
    const float* imB = im + (size_t)c * NMODE + m;
    const float4* xb = (const float4*)g_Xf + (size_t)m * 4;  // [ct][m][b0..7]

    #pragma unroll 4
    for (int ct = 0; ct < 128; ct++) {
        float wre = reA[ct * NMODE] - reB[ct * (128 * NMODE)];
        float wim = imA[ct * NMODE] + imB[ct * (128 * NMODE)];
        const float4* x4 = xb + (size_t)ct * (NMODE * 4);
        float4 x0 = x4[0], x1 = x4[1], x2 = x4[2], x3 = x4[3];
        yr[0]=fmaf(wre,x0.x,fmaf(-wim,x0.y,yr[0])); yi[0]=fmaf(wre,x0.y,fmaf(wim,x0.x,yi[0]));
        yr[1]=fmaf(wre,x0.z,fmaf(-wim,x0.w,yr[1])); yi[1]=fmaf(wre,x0.w,fmaf(wim,x0.z,yi[1]));
        yr[2]=fmaf(wre,x1.x,fmaf(-wim,x1.y,yr[2])); yi[2]=fmaf(wre,x1.y,fmaf(wim,x1.x,yi[2]));
        yr[3]=fmaf(wre,x1.z,fmaf(-wim,x1.w,yr[3])); yi[3]=fmaf(wre,x1.w,fmaf(wim,x1.z,yi[3]));
        yr[4]=fmaf(wre,x2.x,fmaf(-wim,x2.y,yr[4])); yi[4]=fmaf(wre,x2.y,fmaf(wim,x2.x,yi[4]));
        yr[5]=fmaf(wre,x2.z,fmaf(-wim,x2.w,yr[5])); yi[5]=fmaf(wre,x2.w,fmaf(wim,x2.z,yi[5]));
        yr[6]=fmaf(wre,x3.x,fmaf(-wim,x3.y,yr[6])); yi[6]=fmaf(wre,x3.y,fmaf(wim,x3.x,yi[6]));
        yr[7]=fmaf(wre,x3.z,fmaf(-wim,x3.w,yr[7])); yi[7]=fmaf(wre,x3.w,fmaf(wim,x3.z,yi[7]));
    }
    #pragma unroll
    for (int b = 0; b < 8; b++)
        g_Y[(size_t)(b * 128 + c) * NMODE + m] = make_float2(yr[b], yi[b]);
}

// ===========================================================================
// Fused inverse: per (b,c) slice.
// Phase A (kx->h, folded, rotation trig): P[a]=Y[+a]+Y[-a], M[a]=Y[+a]-Y[-a];
//   Z[h]=(C1-S2, C2+S1), Z[128-h]=(C1+S2, C2-S1)  -> Zs in smem.
// Phase B (ky->w c2r): out[h][w] = C - S, out[h][128-w] = C + S,
//   C = sum a_ky Zre cos(t ky w), S = sum a_ky Zim sin(t ky w), a_0=1 else 2.
//   Threads 256..319 do the w=64 column (cos = (-1)^ky, sin = 0).
// ===========================================================================
__global__ __launch_bounds__(320) void k_inv(float* __restrict__ out) {
    __shared__ float2 tb[128];
    __shared__ float2 Pa[17 * NKY];
    __shared__ float2 Ma[17 * NKY];
    __shared__ float2 Zs[128][18];      // pad -> 16B-aligned float4 rows

    const int tid = threadIdx.x;
    if (tid < 128) {
        float s, c;
        sincospif((float)tid * (2.0f / 128.0f), &s, &c);
        tb[tid] = make_float2(c, s);
    }

    const float2* Yp = g_Y + (size_t)blockIdx.x * NMODE;
    if (tid < 17 * NKY) {
        int a = tid / NKY, ky = tid - a * NKY;
        float2 yp = Yp[a * NKY + ky];
        float2 P, M;
        if (a == 0)       { P = yp; M = make_float2(0.f, 0.f); }
        else if (a == 16) { P = yp; M = yp; }
        else {
            float2 yn = Yp[(32 - a) * NKY + ky];
            P = make_float2(yp.x + yn.x, yp.y + yn.y);
            M = make_float2(yp.x - yn.x, yp.y - yn.y);
        }
        Pa[tid] = P;
        Ma[tid] = M;
    }
    __syncthreads();

    // Phase A
    if (tid < 272) {
        const int ky = tid % NKY;
        const int hb = tid / NKY;           // 0..15
        float cw[4], sw[4], tc[4], ts[4];
        float C1[4], C2[4], S1[4], S2[4];
        #pragma unroll
        for (int j = 0; j < 4; j++) {
            int h = hb + 16 * j;
            sincospif((float)h * (1.0f / 64.0f), &sw[j], &cw[j]);  // e^{i 2pi h/128}
            tc[j] = 1.f; ts[j] = 0.f;
            C1[j] = 0.f; C2[j] = 0.f; S1[j] = 0.f; S2[j] = 0.f;
        }
        #pragma unroll
        for (int a = 0; a < NKY; a++) {
            float2 P = Pa[a * NKY + ky];
            float2 M = Ma[a * NKY + ky];
            #pragma unroll
            for (int j = 0; j < 4; j++) {
                C1[j] = fmaf(tc[j], P.x, C1[j]);
                C2[j] = fmaf(tc[j], P.y, C2[j]);
                S1[j] = fmaf(ts[j], M.x, S1[j]);
                S2[j] = fmaf(ts[j], M.y, S2[j]);
                float nc = fmaf(tc[j], cw[j], -ts[j] * sw[j]);
                ts[j] = fmaf(tc[j], sw[j],  ts[j] * cw[j]);
                tc[j] = nc;
            }
        }
        #pragma unroll
        for (int j = 0; j < 4; j++) {
            int h = hb + 16 * j;
            Zs[h][ky] = make_float2(C1[j] - S2[j], C2[j] + S1[j]);
            if (h >= 1)
                Zs[128 - h][ky] = make_float2(C1[j] + S2[j], C2[j] - S1[j]);
        }
    } else if (tid < 289) {
        // h = 64: cos(pi a) = (-1)^a, sin = 0
        const int ky = tid - 272;
        float C1 = 0.f, C2 = 0.f;
        #pragma unroll
        for (int a = 0; a < NKY; a++) {
            float2 P = Pa[a * NKY + ky];
            float sg = (a & 1) ? -1.f : 1.f;
            C1 = fmaf(sg, P.x, C1);
            C2 = fmaf(sg, P.y, C2);
        }
        Zs[64][ky] = make_float2(C1, C2);
    }
    __syncthreads();

    // Phase B
    float* op = out + (size_t)blockIdx.x * 16384;

    if (tid < 256) {
        const int w  = tid & 63;
        const int h0 = (tid >> 6) * 32;
        float ck[NKY], sk[NKY];
        #pragma unroll
        for (int ky = 0; ky < NKY; ky++) {
            float2 t = tb[(ky * w) & 127];
            float a = ky ? 2.0f : 1.0f;
            ck[ky] = a * t.x;
            sk[ky] = a * t.y;
        }
        for (int h = h0; h < h0 + 32; h++) {
            const float4* zp = (const float4*)(&Zs[h][0]);
            float C = 0.f, S = 0.f;
            #pragma unroll
            for (int j = 0; j < 8; j++) {
                float4 q = zp[j];
                C = fmaf(ck[2 * j],     q.x, C);
                S = fmaf(sk[2 * j],     q.y, S);
                C = fmaf(ck[2 * j + 1], q.z, C);
                S = fmaf(sk[2 * j + 1], q.w, S);
            }
            float2 z16 = Zs[h][16];
            C = fmaf(ck[16], z16.x, C);
            S = fmaf(sk[16], z16.y, S);
            op[h * 128 + w] = C - S;
            if (w) op[h * 128 + 128 - w] = C + S;
        }
    } else {
        // w = 64 column: 64 threads x 2 rows
        const int hh = (tid - 256) * 2;
        #pragma unroll
        for (int r = 0; r < 2; r++) {
            int h = hh + r;
            float E = 0.f;
            #pragma unroll
            for (int ky = 0; ky < NKY; ky++) {
                float a = ky ? 2.0f : 1.0f;
                float c = (ky & 1) ? -a : a;
                E = fmaf(c, Zs[h][ky].x, E);
            }
            op[h * 128 + 64] = E;
        }
    }
}

extern "C" void kernel_launch(void* const* d_in, const int* in_sizes, int n_in,
                              void* d_out, int out_size) {
    const float* X  = (const float*)d_in[0];
    const float* re = (const float*)d_in[1];
    const float* im = (const float*)d_in[2];
    float* out = (float*)d_out;

    const int smem_fwd = (64 * 18 + 4) * 8 + 2 * (64 * 65) * 4 + (128 * NKY) * 8;
    cudaFuncSetAttribute(k_fwd, cudaFuncAttributeMaxDynamicSharedMemorySize, smem_fwd);

    k_fwd<<<NSLICE, 320, smem_fwd>>>(X);
    k_mix<<<dim3(17, 16), 256>>>(re, im);
    k_inv<<<NSLICE, 320>>>(out);
}

// round 11
// speedup vs baseline: 1.0652x; 1.0652x over previous
#include <cuda_runtime.h>

// OrbitalSpectralConv: B=8, C=128, H=W=128; kept modes: 32 kx rows x 17 ky cols.
// kx rows: mk 0..16 -> kx = mk; mk 17..31 -> kx = mk+96 == -(32-mk) mod 128.
#define NKY   17
#define NMODE 544           // 32*17
#define NSLICE 1024         // B*C

// Scratch (allocation banned -> device globals).
__device__ float2 g_G [NSLICE * NKY * 128];      // 17.8 MB  [slice][ky][h]
__device__ float2 g_Xf[128 * NMODE * 8];         // 4.45 MB  [c][m][b]
__device__ float2 g_Y [NSLICE * NMODE];          // 4.45 MB  [b][c][m]
__device__ float2 g_Z [NSLICE * 128 * NKY];      // 17.8 MB  [slice][h][ky]

// ===========================================================================
// Kernel 1a: w-DFT per (b,c) slice, DOUBLE-folded (w<->128-w and w<->64-w).
//   G[ky] (even ky=2j): re = Sp0 + Sp64 + (-1)^j Sp32 + sum_{w=1..31} Ae[w] cos
//                       im = -sum Be[w] sin
//   G[ky] (odd ky=2j+1): re = Sp0 - Sp64 + sum Ao[w] cos
//                        im = -(-1)^j Sm32 - sum Bo[w] sin
//   Ae/Ao = Sp[w] +/- Sp[64-w];  Be/Bo = Sm[w] -/+ Sm[64-w]
//   Sp[w] = x[w]+x[128-w], Sm[w] = x[w]-x[128-w].
// Block 256 = 64 h x 4 ky-groups (even 0-8 / even 10-16 / odd 1-7 / odd 9-15).
// ===========================================================================
__global__ __launch_bounds__(256) void k_fwd1(const float* __restrict__ X) {
    __shared__ float2 Te[32][10];   // (cos,sin)(2pi*(2j)*w/128)
    __shared__ float2 To[32][8];    // (cos,sin)(2pi*(2j+1)*w/128)
    __shared__ float  Ae[64][33];   // pad 33 -> conflict-free column access
    __shared__ float  Ao[64][33];
    __shared__ float  Be[64][33];
    __shared__ float  Bo[64][33];
    __shared__ float4 Bd[64];       // (Sp0, Sp64, Sp32, Sm32)

    const int tid = threadIdx.x;
    for (int i = tid; i < 320; i += 256) {
        int w = i / 10, j = i - (i / 10) * 10;
        float s, c;
        sincospif((float)((w * 2 * j) & 127) * (2.0f / 128.0f), &s, &c);
        Te[w][j] = make_float2(c, s);
    }
    {
        int w = tid >> 3, j = tid & 7;
        float s, c;
        sincospif((float)((w * (2 * j + 1)) & 127) * (2.0f / 128.0f), &s, &c);
        To[w][j] = make_float2(c, s);
    }

    const float* Xp = X + (size_t)blockIdx.x * 16384;
    float2* Gp = g_G + (size_t)blockIdx.x * (NKY * 128);

    const int hl  = tid & 63;
    const int grp = tid >> 6;

    for (int half = 0; half < 2; half++) {
        __syncthreads();    // covers trig init (1st) and Ae..Bd reuse (2nd)
        for (int i = tid; i < 2048; i += 256) {
            int hr = i >> 5, w = i & 31;
            const float* row = Xp + (half * 64 + hr) * 128;
            if (w == 0) {
                float x0 = row[0], x64 = row[64], x32 = row[32], x96 = row[96];
                Bd[hr] = make_float4(x0, x64, x32 + x96, x32 - x96);
            } else {
                float xa = row[w], xb = row[64 - w], xc = row[64 + w], xd = row[128 - w];
                float sp  = xa + xd, sm  = xa - xd;      // Sp[w], Sm[w]
                float spb = xb + xc, smb = xb - xc;      // Sp[64-w], Sm[64-w]
                Ae[hr][w] = sp + spb;
                Ao[hr][w] = sp - spb;
                Be[hr][w] = sm - smb;
                Bo[hr][w] = sm + smb;
            }
        }
        __syncthreads();

        const float4 bd = Bd[hl];
        const int h = half * 64 + hl;

        if (grp == 0) {                       // even ky 0,2,4,6,8
            float gr[5], gi[5];
            #pragma unroll
            for (int j = 0; j < 5; j++) {
                gr[j] = bd.x + bd.y + ((j & 1) ? -bd.z : bd.z);
                gi[j] = 0.f;
            }
            #pragma unroll 4
            for (int w = 1; w < 32; w++) {
                float a  = Ae[hl][w];
                float nb = -Be[hl][w];
                float4 t01 = *(const float4*)&Te[w][0];
                float4 t23 = *(const float4*)&Te[w][2];
                float2 t4  = Te[w][4];
                gr[0]=fmaf(t01.x,a,gr[0]); gi[0]=fmaf(t01.y,nb,gi[0]);
                gr[1]=fmaf(t01.z,a,gr[1]); gi[1]=fmaf(t01.w,nb,gi[1]);
                gr[2]=fmaf(t23.x,a,gr[2]); gi[2]=fmaf(t23.y,nb,gi[2]);
                gr[3]=fmaf(t23.z,a,gr[3]); gi[3]=fmaf(t23.w,nb,gi[3]);
                gr[4]=fmaf(t4.x ,a,gr[4]); gi[4]=fmaf(t4.y ,nb,gi[4]);
            }
            #pragma unroll
            for (int j = 0; j < 5; j++)
                Gp[(2 * j) * 128 + h] = make_float2(gr[j], gi[j]);
        } else if (grp == 1) {                // even ky 10,12,14,16 (j=5..8)
            float gr[4], gi[4];
            #pragma unroll
            for (int j = 0; j < 4; j++) {
                int jj = 5 + j;
                gr[j] = bd.x + bd.y + ((jj & 1) ? -bd.z : bd.z);
                gi[j] = 0.f;
            }
            #pragma unroll 4
            for (int w = 1; w < 32; w++) {
                float a  = Ae[hl][w];
                float nb = -Be[hl][w];
                float2 t5  = Te[w][5];
                float4 t67 = *(const float4*)&Te[w][6];
                float2 t8  = Te[w][8];
                gr[0]=fmaf(t5.x ,a,gr[0]); gi[0]=fmaf(t5.y ,nb,gi[0]);
                gr[1]=fmaf(t67.x,a,gr[1]); gi[1]=fmaf(t67.y,nb,gi[1]);
                gr[2]=fmaf(t67.z,a,gr[2]); gi[2]=fmaf(t67.w,nb,gi[2]);
                gr[3]=fmaf(t8.x ,a,gr[3]); gi[3]=fmaf(t8.y ,nb,gi[3]);
            }
            #pragma unroll
            for (int j = 0; j < 4; j++)
                Gp[(10 + 2 * j) * 128 + h] = make_float2(gr[j], gi[j]);
        } else if (grp == 2) {                // odd ky 1,3,5,7 (j=0..3)
            float gr[4], gi[4];
            #pragma unroll
            for (int j = 0; j < 4; j++) {
                gr[j] = bd.x - bd.y;
                gi[j] = (j & 1) ? bd.w : -bd.w;      // -(-1)^j Sm32
            }
            #pragma unroll 4
            for (int w = 1; w < 32; w++) {
                float a  = Ao[hl][w];
                float nb = -Bo[hl][w];
                float4 t01 = *(const float4*)&To[w][0];
                float4 t23 = *(const float4*)&To[w][2];
                gr[0]=fmaf(t01.x,a,gr[0]); gi[0]=fmaf(t01.y,nb,gi[0]);
                gr[1]=fmaf(t01.z,a,gr[1]); gi[1]=fmaf(t01.w,nb,gi[1]);
                gr[2]=fmaf(t23.x,a,gr[2]); gi[2]=fmaf(t23.y,nb,gi[2]);
                gr[3]=fmaf(t23.z,a,gr[3]); gi[3]=fmaf(t23.w,nb,gi[3]);
            }
            #pragma unroll
            for (int j = 0; j < 4; j++)
                Gp[(2 * j + 1) * 128 + h] = make_float2(gr[j], gi[j]);
        } else {                              // odd ky 9,11,13,15 (j=4..7)
            float gr[4], gi[4];
            #pragma unroll
            for (int j = 0; j < 4; j++) {
                int jj = 4 + j;
                gr[j] = bd.x - bd.y;
                gi[j] = (jj & 1) ? bd.w : -bd.w;
            }
            #pragma unroll 4
            for (int w = 1; w < 32; w++) {
                float a  = Ao[hl][w];
                float nb = -Bo[hl][w];
                float4 t45 = *(const float4*)&To[w][4];
                float4 t67 = *(const float4*)&To[w][6];
                gr[0]=fmaf(t45.x,a,gr[0]); gi[0]=fmaf(t45.y,nb,gi[0]);
                gr[1]=fmaf(t45.z,a,gr[1]); gi[1]=fmaf(t45.w,nb,gi[1]);
                gr[2]=fmaf(t67.x,a,gr[2]); gi[2]=fmaf(t67.y,nb,gi[2]);
                gr[3]=fmaf(t67.z,a,gr[3]); gi[3]=fmaf(t67.w,nb,gi[3]);
            }
            #pragma unroll
            for (int j = 0; j < 4; j++)
                Gp[(9 + 2 * j) * 128 + h] = make_float2(gr[j], gi[j]);
        }
    }
}

// ===========================================================================
// Kernel 1b: h-DFT, folded, 2 slices per block, rotation-generated trig.
//   Xf[+a]=(C1+S2, C2-S1), Xf[-a]=(C1-S2, C2+S1), scaled 1/16384.
// ===========================================================================
__global__ __launch_bounds__(320) void k_fwd2() {
    __shared__ float2 Gs[2][128 * NKY];     // [slice][h][ky]

    const int tid = threadIdx.x;
    const int s0  = blockIdx.x * 2;

    #pragma unroll
    for (int k = 0; k < 2; k++) {
        const float2* Gp = g_G + (size_t)(s0 + k) * (NKY * 128);
        for (int i = tid; i < NKY * 128; i += 320) {
            int ky = i >> 7, h = i & 127;
            Gs[k][h * NKY + ky] = Gp[i];    // coalesced read, conflict-free write
        }
    }
    __syncthreads();

    if (tid < 17 * NKY) {
        const int a = tid / NKY, ky = tid - a * NKY;
        float cw, sw;
        sincospif((float)a * (1.0f / 64.0f), &sw, &cw);   // e^{i 2pi a/128}

        float C1[2], C2[2], S1[2], S2[2];
        const float sgn = (a & 1) ? -1.f : 1.f;
        #pragma unroll
        for (int k = 0; k < 2; k++) {
            float2 g0  = Gs[k][0 * NKY + ky];
            float2 g64 = Gs[k][64 * NKY + ky];
            C1[k] = g0.x + sgn * g64.x;
            C2[k] = g0.y + sgn * g64.y;
            S1[k] = 0.f; S2[k] = 0.f;
        }

        float tc = cw, ts = sw;
        #pragma unroll 3
        for (int h = 1; h < 64; h++) {
            #pragma unroll
            for (int k = 0; k < 2; k++) {
                float2 ga = Gs[k][h * NKY + ky];
                float2 gb = Gs[k][(128 - h) * NKY + ky];
                float pr = ga.x + gb.x, pi = ga.y + gb.y;
                float mr = ga.x - gb.x, mi = ga.y - gb.y;
                C1[k] = fmaf(tc, pr, C1[k]);
                C2[k] = fmaf(tc, pi, C2[k]);
                S1[k] = fmaf(ts, mr, S1[k]);
                S2[k] = fmaf(ts, mi, S2[k]);
            }
            float nc = fmaf(tc, cw, -ts * sw);
            ts = fmaf(tc, sw,  ts * cw);
            tc = nc;
        }

        const float inv = 1.0f / 16384.0f;
        #pragma unroll
        for (int k = 0; k < 2; k++) {
            const int s = s0 + k, b = s >> 7, c = s & 127;
            float2* Xfb = g_Xf + (size_t)c * (NMODE * 8) + b;
            Xfb[(a * NKY + ky) * 8] =
                make_float2((C1[k] + S2[k]) * inv, (C2[k] - S1[k]) * inv);
            if (a >= 1 && a <= 15)
                Xfb[((32 - a) * NKY + ky) * 8] =
                    make_float2((C1[k] - S2[k]) * inv, (C2[k] + S1[k]) * inv);
        }
    }
}

// ===========================================================================
// Kernel 2: spectral channel mix, skew-Hermitian weight built on the fly.
//   Y[b,c,m] = sum_ct [(re[c,ct,m]-re[ct,c,m]) + i(im[c,ct,m]+im[ct,c,m])] Xf[b,ct,m]
// ===========================================================================
__global__ __launch_bounds__(256) void k_mix(const float* __restrict__ re,
                                             const float* __restrict__ im) {
    const int mi = threadIdx.x & 31;
    const int ci = threadIdx.x >> 5;
    const int m  = blockIdx.x * 32 + mi;
    const int c  = blockIdx.y * 8 + ci;

    float yr[8], yi[8];
    #pragma unroll
    for (int b = 0; b < 8; b++) { yr[b] = 0.f; yi[b] = 0.f; }

    const float* reA = re + (size_t)c * (128 * NMODE) + m;   // [c][ct][m]
    const float* reB = re + (size_t)c * NMODE + m;           // [ct][c][m]
    const float* imA = im + (size_t)c * (128 * NMODE) + m;
    const float* imB = im + (size_t)c * NMODE + m;
    const float4* xb = (const float4*)g_Xf + (size_t)m * 4;  // [ct][m][b0..7]

    #pragma unroll 4
    for (int ct = 0; ct < 128; ct++) {
        float wre = reA[ct * NMODE] - reB[ct * (128 * NMODE)];
        float wim = imA[ct * NMODE] + imB[ct * (128 * NMODE)];
        const float4* x4 = xb + (size_t)ct * (NMODE * 4);
        float4 x0 = x4[0], x1 = x4[1], x2 = x4[2], x3 = x4[3];
        yr[0]=fmaf(wre,x0.x,fmaf(-wim,x0.y,yr[0])); yi[0]=fmaf(wre,x0.y,fmaf(wim,x0.x,yi[0]));
        yr[1]=fmaf(wre,x0.z,fmaf(-wim,x0.w,yr[1])); yi[1]=fmaf(wre,x0.w,fmaf(wim,x0.z,yi[1]));
        yr[2]=fmaf(wre,x1.x,fmaf(-wim,x1.y,yr[2])); yi[2]=fmaf(wre,x1.y,fmaf(wim,x1.x,yi[2]));
        yr[3]=fmaf(wre,x1.z,fmaf(-wim,x1.w,yr[3])); yi[3]=fmaf(wre,x1.w,fmaf(wim,x1.z,yi[3]));
        yr[4]=fmaf(wre,x2.x,fmaf(-wim,x2.y,yr[4])); yi[4]=fmaf(wre,x2.y,fmaf(wim,x2.x,yi[4]));
        yr[5]=fmaf(wre,x2.z,fmaf(-wim,x2.w,yr[5])); yi[5]=fmaf(wre,x2.w,fmaf(wim,x2.z,yi[5]));
        yr[6]=fmaf(wre,x3.x,fmaf(-wim,x3.y,yr[6])); yi[6]=fmaf(wre,x3.y,fmaf(wim,x3.x,yi[6]));
        yr[7]=fmaf(wre,x3.z,fmaf(-wim,x3.w,yr[7])); yi[7]=fmaf(wre,x3.w,fmaf(wim,x3.z,yi[7]));
    }
    #pragma unroll
    for (int b = 0; b < 8; b++)
        g_Y[(size_t)(b * 128 + c) * NMODE + m] = make_float2(yr[b], yi[b]);
}

// ===========================================================================
// Kernel 3a: kx -> h synthesis (folded), rotation trig, 4 h per thread.
//   Z[h]=(C1-S2, C2+S1), Z[128-h]=(C1+S2, C2-S1)
// ===========================================================================
__global__ __launch_bounds__(320) void k_inv1() {
    __shared__ float2 Pa[17 * NKY];
    __shared__ float2 Ma[17 * NKY];

    const int tid = threadIdx.x;
    const float2* Yp = g_Y + (size_t)blockIdx.x * NMODE;

    if (tid < 17 * NKY) {
        int a = tid / NKY, ky = tid - a * NKY;
        float2 yp = Yp[a * NKY + ky];
        float2 P, M;
        if (a == 0)       { P = yp; M = make_float2(0.f, 0.f); }
        else if (a == 16) { P = yp; M = yp; }
        else {
            float2 yn = Yp[(32 - a) * NKY + ky];
            P = make_float2(yp.x + yn.x, yp.y + yn.y);
            M = make_float2(yp.x - yn.x, yp.y - yn.y);
        }
        Pa[tid] = P;
        Ma[tid] = M;
    }
    __syncthreads();

    float2* Zp = g_Z + (size_t)blockIdx.x * (128 * NKY);

    if (tid < 272) {
        const int ky = tid % NKY;
        const int hb = tid / NKY;           // 0..15
        float cw[4], sw[4], tc[4], ts[4];
        float C1[4], C2[4], S1[4], S2[4];
        #pragma unroll
        for (int j = 0; j < 4; j++) {
            int h = hb + 16 * j;
            sincospif((float)h * (1.0f / 64.0f), &sw[j], &cw[j]);
            tc[j] = 1.f; ts[j] = 0.f;
            C1[j] = 0.f; C2[j] = 0.f; S1[j] = 0.f; S2[j] = 0.f;
        }
        #pragma unroll
        for (int a = 0; a < NKY; a++) {
            float2 P = Pa[a * NKY + ky];
            float2 M = Ma[a * NKY + ky];
            #pragma unroll
            for (int j = 0; j < 4; j++) {
                C1[j] = fmaf(tc[j], P.x, C1[j]);
                C2[j] = fmaf(tc[j], P.y, C2[j]);
                S1[j] = fmaf(ts[j], M.x, S1[j]);
                S2[j] = fmaf(ts[j], M.y, S2[j]);
                float nc = fmaf(tc[j], cw[j], -ts[j] * sw[j]);
                ts[j] = fmaf(tc[j], sw[j],  ts[j] * cw[j]);
                tc[j] = nc;
            }
        }
        #pragma unroll
        for (int j = 0; j < 4; j++) {
            int h = hb + 16 * j;
            Zp[h * NKY + ky] = make_float2(C1[j] - S2[j], C2[j] + S1[j]);
            if (h >= 1)
                Zp[(128 - h) * NKY + ky] = make_float2(C1[j] + S2[j], C2[j] - S1[j]);
        }
    } else if (tid < 289) {
        const int ky = tid - 272;           // h = 64: cos(pi a)=(-1)^a, sin=0
        float C1 = 0.f, C2 = 0.f;
        #pragma unroll
        for (int a = 0; a < NKY; a++) {
            float2 P = Pa[a * NKY + ky];
            float sg = (a & 1) ? -1.f : 1.f;
            C1 = fmaf(sg, P.x, C1);
            C2 = fmaf(sg, P.y, C2);
        }
        Zp[64 * NKY + ky] = make_float2(C1, C2);
    }
}

// ===========================================================================
// Kernel 3b: ky -> w c2r synthesis, QUARTER-folded: thread (h, w<=31) emits
// out at w, 128-w, 64-w, 64+w from even/odd ky partial sums:
//   out[w]     = (Ce+Co) - (Se+So)      out[128-w] = (Ce+Co) + (Se+So)
//   out[64-w]  = (Ce-Co) + (Se-So)      out[64+w]  = (Ce-Co) - (Se-So)
// w=0 thread additionally emits w=32 and w=96:
//   C32 = sum_j a_{2j}(-1)^j Zre_ev[j],  S32 = sum_j 2(-1)^j Zim_od[j]
//   out[32] = C32 - S32, out[96] = C32 + S32.
// ===========================================================================
__global__ __launch_bounds__(256) void k_inv2(float* __restrict__ out) {
    __shared__ float2 tb[128];
    __shared__ float2 Zev[128][10];     // even ky j=0..8 (pad 10: 16B-aligned rows)
    __shared__ float2 Zod[128][8];      // odd  ky j=0..7

    const int tid = threadIdx.x;
    if (tid < 128) {
        float s, c;
        sincospif((float)tid * (2.0f / 128.0f), &s, &c);
        tb[tid] = make_float2(c, s);
    }
    const float2* Zp = g_Z + (size_t)blockIdx.x * (128 * NKY);
    for (int i = tid; i < 128 * NKY; i += 256) {
        int h = i / NKY, ky = i - h * NKY;
        float2 z = Zp[i];
        if (ky & 1) Zod[h][ky >> 1] = z;
        else        Zev[h][ky >> 1] = z;
    }
    __syncthreads();

    const int w  = tid & 31;
    const int h0 = (tid >> 5) * 16;
    float ck[NKY], sk[NKY];
    #pragma unroll
    for (int ky = 0; ky < NKY; ky++) {
        float2 t = tb[(ky * w) & 127];
        float a = ky ? 2.0f : 1.0f;
        ck[ky] = a * t.x;
        sk[ky] = a * t.y;
    }

    float* op = out + (size_t)blockIdx.x * 16384;
    for (int h = h0; h < h0 + 16; h++) {
        float4 e01 = *(const float4*)&Zev[h][0];
        float4 e23 = *(const float4*)&Zev[h][2];
        float4 e45 = *(const float4*)&Zev[h][4];
        float4 e67 = *(const float4*)&Zev[h][6];
        float2 e8  = Zev[h][8];
        float4 o01 = *(const float4*)&Zod[h][0];
        float4 o23 = *(const float4*)&Zod[h][2];
        float4 o45 = *(const float4*)&Zod[h][4];
        float4 o67 = *(const float4*)&Zod[h][6];

        float Ce = ck[0] * e01.x;          float Se = sk[0] * e01.y;
        Ce = fmaf(ck[2],  e01.z, Ce);      Se = fmaf(sk[2],  e01.w, Se);
        Ce = fmaf(ck[4],  e23.x, Ce);      Se = fmaf(sk[4],  e23.y, Se);
        Ce = fmaf(ck[6],  e23.z, Ce);      Se = fmaf(sk[6],  e23.w, Se);
        Ce = fmaf(ck[8],  e45.x, Ce);      Se = fmaf(sk[8],  e45.y, Se);
        Ce = fmaf(ck[10], e45.z, Ce);      Se = fmaf(sk[10], e45.w, Se);
        Ce = fmaf(ck[12], e67.x, Ce);      Se = fmaf(sk[12], e67.y, Se);
        Ce = fmaf(ck[14], e67.z, Ce);      Se = fmaf(sk[14], e67.w, Se);
        Ce = fmaf(ck[16], e8.x,  Ce);      Se = fmaf(sk[16], e8.y,  Se);

        float Co = ck[1] * o01.x;          float So = sk[1] * o01.y;
        Co = fmaf(ck[3],  o01.z, Co);      So = fmaf(sk[3],  o01.w, So);
        Co = fmaf(ck[5],  o23.x, Co);      So = fmaf(sk[5],  o23.y, So);
        Co = fmaf(ck[7],  o23.z, Co);      So = fmaf(sk[7],  o23.w, So);
        Co = fmaf(ck[9],  o45.x, Co);      So = fmaf(sk[9],  o45.y, So);
        Co = fmaf(ck[11], o45.z, Co);      So = fmaf(sk[11], o45.w, So);
        Co = fmaf(ck[13], o67.x, Co);      So = fmaf(sk[13], o67.y, So);
        Co = fmaf(ck[15], o67.z, Co);      So = fmaf(sk[15], o67.w, So);

        float Cp = Ce + Co, Cm = Ce - Co;
        float Sp = Se + So, Sm = Se - So;
        float* oph = op + h * 128;
        oph[w] = Cp - Sp;
        if (w) {
            oph[128 - w] = Cp + Sp;
            oph[64 - w]  = Cm + Sm;
            oph[64 + w]  = Cm - Sm;
        } else {
            oph[64] = Cm;
            // w = 32 / 96 columns (self-paired under the w<->64-w fold):
            // even ky=2j: cos(pi j) = (-1)^j, sin = 0
            // odd  ky=2j+1: cos = 0, sin(pi(2j+1)/2) = (-1)^j
            float C32 = e01.x;                 // j0, a=1
            C32 = fmaf(-2.f, e01.z, C32);      // j1
            C32 = fmaf( 2.f, e23.x, C32);      // j2
            C32 = fmaf(-2.f, e23.z, C32);      // j3
            C32 = fmaf( 2.f, e45.x, C32);      // j4
            C32 = fmaf(-2.f, e45.z, C32);      // j5
            C32 = fmaf( 2.f, e67.x, C32);      // j6
            C32 = fmaf(-2.f, e67.z, C32);      // j7
            C32 = fmaf( 2.f, e8.x,  C32);      // j8
            float S32 = o01.y - o01.w + o23.y - o23.w
                      + o45.y - o45.w + o67.y - o67.w;
            S32 *= 2.f;
            oph[32] = C32 - S32;
            oph[96] = C32 + S32;
        }
    }
}

extern "C" void kernel_launch(void* const* d_in, const int* in_sizes, int n_in,
                              void* d_out, int out_size) {
    const float* X  = (const float*)d_in[0];
    const float* re = (const float*)d_in[1];
    const float* im = (const float*)d_in[2];
    float* out = (float*)d_out;

    k_fwd1<<<NSLICE, 256>>>(X);
    k_fwd2<<<NSLICE / 2, 320>>>();
    k_mix<<<dim3(17, 16), 256>>>(re, im);
    k_inv1<<<NSLICE, 320>>>();
    k_inv2<<<NSLICE, 256>>>(out);
}

// round 12
// speedup vs baseline: 1.1358x; 1.0663x over previous
#include <cuda_runtime.h>

// OrbitalSpectralConv: B=8, C=128, H=W=128; kept modes: 32 kx rows x 17 ky cols.
// kx rows: mk 0..16 -> kx = mk; mk 17..31 -> kx = mk+96 == -(32-mk) mod 128.
#define NKY   17
#define NMODE 544           // 32*17
#define NSLICE 1024         // B*C

// Scratch (allocation banned -> device globals).
__device__ float2 g_Xf[128 * NMODE * 8];         // 4.45 MB  [c][m][b]
__device__ float2 g_Y [NSLICE * NMODE];          // 4.45 MB  [b][c][m]

// ===========================================================================
// Fused forward per (b,c) slice. 320 threads, 56832 B dynamic smem.
// Phase A (w-DFT, DOUBLE-folded, 256 threads = 64 h x 4 ky-groups):
//   even ky=2j: re = Sp0+Sp64+(-1)^j Sp32 + sum_{w=1..31} Ae[w] cos; im = -sum Be sin
//   odd  ky=2j+1: re = Sp0-Sp64 + sum Ao cos; im = -(-1)^j Sm32 - sum Bo sin
//   Ae/Ao = Sp[w] +/- Sp[64-w]; Be/Bo = Sm[w] -/+ Sm[64-w];
//   Sp[w]=x[w]+x[128-w], Sm[w]=x[w]-x[128-w].      -> Gs[h][ky] in smem
// Phase B (h-DFT, folded, rotation trig, 289 threads = (a,ky)):
//   C1=sum cos(ah)Gp_re, C2=sum cos(ah)Gp_im, S1=sum sin(ah)Gm_re, S2=..im
//   Xf[+a]=(C1+S2, C2-S1), Xf[-a]=(C1-S2, C2+S1), scaled 1/16384 -> g_Xf[c][m][b]
// ===========================================================================
__global__ __launch_bounds__(320) void k_fwd(const float* __restrict__ X) {
    extern __shared__ char smraw[];
    float4* Bd = (float4*)smraw;                 // [64]   (Sp0, Sp64, Sp32, Sm32)
    float2* Te = (float2*)(Bd + 64);             // [32][10] cos/sin(2pi*2j*w/128)
    float2* To = Te + 32 * 10;                   // [32][8]  cos/sin(2pi*(2j+1)*w/128)
    float2* Gs = To + 32 * 8;                    // [128][17]
    float*  Ae = (float*)(Gs + 128 * NKY);       // [64][33]
    float*  Ao = Ae + 64 * 33;
    float*  Be = Ao + 64 * 33;
    float*  Bo = Be + 64 * 33;

    const int tid = threadIdx.x;

    if (tid < 320) {
        int w = tid / 10, j = tid - (tid / 10) * 10;
        float s, c;
        sincospif((float)((w * 2 * j) & 127) * (2.0f / 128.0f), &s, &c);
        Te[tid] = make_float2(c, s);
    }
    if (tid < 256) {
        int w = tid >> 3, j = tid & 7;
        float s, c;
        sincospif((float)((w * (2 * j + 1)) & 127) * (2.0f / 128.0f), &s, &c);
        To[tid] = make_float2(c, s);
    }

    const float* Xp = X + (size_t)blockIdx.x * 16384;

    const int hl  = tid & 63;
    const int grp = tid >> 6;

    for (int half = 0; half < 2; half++) {
        __syncthreads();    // covers trig init (1st) and Ae..Bd reuse (2nd)
        for (int i = tid; i < 2048; i += 320) {
            int hr = i >> 5, w = i & 31;
            const float* row = Xp + (half * 64 + hr) * 128;
            if (w == 0) {
                float x0 = row[0], x64 = row[64], x32 = row[32], x96 = row[96];
                Bd[hr] = make_float4(x0, x64, x32 + x96, x32 - x96);
            } else {
                float xa = row[w], xb = row[64 - w], xc = row[64 + w], xd = row[128 - w];
                float sp  = xa + xd, sm  = xa - xd;
                float spb = xb + xc, smb = xb - xc;
                Ae[hr * 33 + w] = sp + spb;
                Ao[hr * 33 + w] = sp - spb;
                Be[hr * 33 + w] = sm - smb;
                Bo[hr * 33 + w] = sm + smb;
            }
        }
        __syncthreads();

        if (grp < 4) {
            const float4 bd = Bd[hl];
            const int h = half * 64 + hl;

            if (grp == 0) {                       // even ky 0,2,4,6,8
                float gr[5], gi[5];
                #pragma unroll
                for (int j = 0; j < 5; j++) {
                    gr[j] = bd.x + bd.y + ((j & 1) ? -bd.z : bd.z);
                    gi[j] = 0.f;
                }
                #pragma unroll 4
                for (int w = 1; w < 32; w++) {
                    float a  = Ae[hl * 33 + w];
                    float nb = -Be[hl * 33 + w];
                    float4 t01 = *(const float4*)(Te + w * 10);
                    float4 t23 = *(const float4*)(Te + w * 10 + 2);
                    float2 t4  = Te[w * 10 + 4];
                    gr[0]=fmaf(t01.x,a,gr[0]); gi[0]=fmaf(t01.y,nb,gi[0]);
                    gr[1]=fmaf(t01.z,a,gr[1]); gi[1]=fmaf(t01.w,nb,gi[1]);
                    gr[2]=fmaf(t23.x,a,gr[2]); gi[2]=fmaf(t23.y,nb,gi[2]);
                    gr[3]=fmaf(t23.z,a,gr[3]); gi[3]=fmaf(t23.w,nb,gi[3]);
                    gr[4]=fmaf(t4.x ,a,gr[4]); gi[4]=fmaf(t4.y ,nb,gi[4]);
                }
                #pragma unroll
                for (int j = 0; j < 5; j++)
                    Gs[h * NKY + 2 * j] = make_float2(gr[j], gi[j]);
            } else if (grp == 1) {                // even ky 10,12,14,16 (j=5..8)
                float gr[4], gi[4];
                #pragma unroll
                for (int j = 0; j < 4; j++) {
                    int jj = 5 + j;
                    gr[j] = bd.x + bd.y + ((jj & 1) ? -bd.z : bd.z);
                    gi[j] = 0.f;
                }
                #pragma unroll 4
                for (int w = 1; w < 32; w++) {
                    float a  = Ae[hl * 33 + w];
                    float nb = -Be[hl * 33 + w];
                    float2 t5  = Te[w * 10 + 5];
                    float4 t67 = *(const float4*)(Te + w * 10 + 6);
                    float2 t8  = Te[w * 10 + 8];
                    gr[0]=fmaf(t5.x ,a,gr[0]); gi[0]=fmaf(t5.y ,nb,gi[0]);
                    gr[1]=fmaf(t67.x,a,gr[1]); gi[1]=fmaf(t67.y,nb,gi[1]);
                    gr[2]=fmaf(t67.z,a,gr[2]); gi[2]=fmaf(t67.w,nb,gi[2]);
                    gr[3]=fmaf(t8.x ,a,gr[3]); gi[3]=fmaf(t8.y ,nb,gi[3]);
                }
                #pragma unroll
                for (int j = 0; j < 4; j++)
                    Gs[h * NKY + 10 + 2 * j] = make_float2(gr[j], gi[j]);
            } else if (grp == 2) {                // odd ky 1,3,5,7 (j=0..3)
                float gr[4], gi[4];
                #pragma unroll
                for (int j = 0; j < 4; j++) {
                    gr[j] = bd.x - bd.y;
                    gi[j] = (j & 1) ? bd.w : -bd.w;
                }
                #pragma unroll 4
                for (int w = 1; w < 32; w++) {
                    float a  = Ao[hl * 33 + w];
                    float nb = -Bo[hl * 33 + w];
                    float4 t01 = *(const float4*)(To + w * 8);
                    float4 t23 = *(const float4*)(To + w * 8 + 2);
                    gr[0]=fmaf(t01.x,a,gr[0]); gi[0]=fmaf(t01.y,nb,gi[0]);
                    gr[1]=fmaf(t01.z,a,gr[1]); gi[1]=fmaf(t01.w,nb,gi[1]);
                    gr[2]=fmaf(t23.x,a,gr[2]); gi[2]=fmaf(t23.y,nb,gi[2]);
                    gr[3]=fmaf(t23.z,a,gr[3]); gi[3]=fmaf(t23.w,nb,gi[3]);
                }
                #pragma unroll
                for (int j = 0; j < 4; j++)
                    Gs[h * NKY + 2 * j + 1] = make_float2(gr[j], gi[j]);
            } else {                              // odd ky 9,11,13,15 (j=4..7)
                float gr[4], gi[4];
                #pragma unroll
                for (int j = 0; j < 4; j++) {
                    int jj = 4 + j;
                    gr[j] = bd.x - bd.y;
                    gi[j] = (jj & 1) ? bd.w : -bd.w;
                }
                #pragma unroll 4
                for (int w = 1; w < 32; w++) {
                    float a  = Ao[hl * 33 + w];
                    float nb = -Bo[hl * 33 + w];
                    float4 t45 = *(const float4*)(To + w * 8 + 4);
                    float4 t67 = *(const float4*)(To + w * 8 + 6);
                    gr[0]=fmaf(t45.x,a,gr[0]); gi[0]=fmaf(t45.y,nb,gi[0]);
                    gr[1]=fmaf(t45.z,a,gr[1]); gi[1]=fmaf(t45.w,nb,gi[1]);
                    gr[2]=fmaf(t67.x,a,gr[2]); gi[2]=fmaf(t67.y,nb,gi[2]);
                    gr[3]=fmaf(t67.z,a,gr[3]); gi[3]=fmaf(t67.w,nb,gi[3]);
                }
                #pragma unroll
                for (int j = 0; j < 4; j++)
                    Gs[h * NKY + 9 + 2 * j] = make_float2(gr[j], gi[j]);
            }
        }
    }
    __syncthreads();

    // Phase B: h-DFT, folded, rotation trig.
    if (tid < 17 * NKY) {
        const int a = tid / NKY, ky = tid - a * NKY;
        float cw, sw;
        sincospif((float)a * (1.0f / 64.0f), &sw, &cw);   // e^{i 2pi a/128}

        float2 g0  = Gs[0 * NKY + ky];
        float2 g64 = Gs[64 * NKY + ky];
        const float sgn = (a & 1) ? -1.f : 1.f;
        float C1 = g0.x + sgn * g64.x;
        float C2 = g0.y + sgn * g64.y;
        float S1 = 0.f, S2 = 0.f;

        float tc = cw, ts = sw;
        #pragma unroll 3
        for (int h = 1; h < 64; h++) {
            float2 ga = Gs[h * NKY + ky];
            float2 gb = Gs[(128 - h) * NKY + ky];
            float pr = ga.x + gb.x, pi = ga.y + gb.y;
            float mr = ga.x - gb.x, mi = ga.y - gb.y;
            C1 = fmaf(tc, pr, C1);
            C2 = fmaf(tc, pi, C2);
            S1 = fmaf(ts, mr, S1);
            S2 = fmaf(ts, mi, S2);
            float nc = fmaf(tc, cw, -ts * sw);
            ts = fmaf(tc, sw,  ts * cw);
            tc = nc;
        }

        const float inv = 1.0f / 16384.0f;
        const int b = blockIdx.x >> 7, c = blockIdx.x & 127;
        float2* Xfb = g_Xf + (size_t)c * (NMODE * 8) + b;
        Xfb[(a * NKY + ky) * 8] = make_float2((C1 + S2) * inv, (C2 - S1) * inv);
        if (a >= 1 && a <= 15)
            Xfb[((32 - a) * NKY + ky) * 8] =
                make_float2((C1 - S2) * inv, (C2 + S1) * inv);
    }
}

// ===========================================================================
// Kernel 2: spectral channel mix, skew-Hermitian weight built on the fly.
//   Y[b,c,m] = sum_ct [(re[c,ct,m]-re[ct,c,m]) + i(im[c,ct,m]+im[ct,c,m])] Xf[b,ct,m]
// ===========================================================================
__global__ __launch_bounds__(256) void k_mix(const float* __restrict__ re,
                                             const float* __restrict__ im) {
    const int mi = threadIdx.x & 31;
    const int ci = threadIdx.x >> 5;
    const int m  = blockIdx.x * 32 + mi;
    const int c  = blockIdx.y * 8 + ci;

    float yr[8], yi[8];
    #pragma unroll
    for (int b = 0; b < 8; b++) { yr[b] = 0.f; yi[b] = 0.f; }

    const float* reA = re + (size_t)c * (128 * NMODE) + m;   // [c][ct][m]
    const float* reB = re + (size_t)c * NMODE + m;           // [ct][c][m]
    const float* imA = im + (size_t)c * (128 * NMODE) + m;
    const float* imB = im + (size_t)c * NMODE + m;
    const float4* xb = (const float4*)g_Xf + (size_t)m * 4;  // [ct][m][b0..7]

    #pragma unroll 4
    for (int ct = 0; ct < 128; ct++) {
        float wre = reA[ct * NMODE] - reB[ct * (128 * NMODE)];
        float wim = imA[ct * NMODE] + imB[ct * (128 * NMODE)];
        const float4* x4 = xb + (size_t)ct * (NMODE * 4);
        float4 x0 = x4[0], x1 = x4[1], x2 = x4[2], x3 = x4[3];
        yr[0]=fmaf(wre,x0.x,fmaf(-wim,x0.y,yr[0])); yi[0]=fmaf(wre,x0.y,fmaf(wim,x0.x,yi[0]));
        yr[1]=fmaf(wre,x0.z,fmaf(-wim,x0.w,yr[1])); yi[1]=fmaf(wre,x0.w,fmaf(wim,x0.z,yi[1]));
        yr[2]=fmaf(wre,x1.x,fmaf(-wim,x1.y,yr[2])); yi[2]=fmaf(wre,x1.y,fmaf(wim,x1.x,yi[2]));
        yr[3]=fmaf(wre,x1.z,fmaf(-wim,x1.w,yr[3])); yi[3]=fmaf(wre,x1.w,fmaf(wim,x1.z,yi[3]));
        yr[4]=fmaf(wre,x2.x,fmaf(-wim,x2.y,yr[4])); yi[4]=fmaf(wre,x2.y,fmaf(wim,x2.x,yi[4]));
        yr[5]=fmaf(wre,x2.z,fmaf(-wim,x2.w,yr[5])); yi[5]=fmaf(wre,x2.w,fmaf(wim,x2.z,yi[5]));
        yr[6]=fmaf(wre,x3.x,fmaf(-wim,x3.y,yr[6])); yi[6]=fmaf(wre,x3.y,fmaf(wim,x3.x,yi[6]));
        yr[7]=fmaf(wre,x3.z,fmaf(-wim,x3.w,yr[7])); yi[7]=fmaf(wre,x3.w,fmaf(wim,x3.z,yi[7]));
    }
    #pragma unroll
    for (int b = 0; b < 8; b++)
        g_Y[(size_t)(b * 128 + c) * NMODE + m] = make_float2(yr[b], yi[b]);
}

// ===========================================================================
// Fused inverse per (b,c) slice. 320 threads.
// Phase A (kx->h, folded, rotation trig, 272+17 threads):
//   P[a]=Y[+a]+Y[-a], M[a]=Y[+a]-Y[-a];
//   Z[h]=(C1-S2, C2+S1), Z[128-h]=(C1+S2, C2-S1)  -> Zev/Zod (ky parity-split)
// Phase B (ky->w c2r, QUARTER-folded, 256 threads): thread (h, w<=31) emits
//   out[w]=(Ce+Co)-(Se+So), out[128-w]=(Ce+Co)+(Se+So),
//   out[64-w]=(Ce-Co)+(Se-So), out[64+w]=(Ce-Co)-(Se-So);
//   w=0 also emits w=32/96 via C32 = sum a_2j (-1)^j Zre_ev, S32 = 2 sum (-1)^j Zim_od.
// ===========================================================================
__global__ __launch_bounds__(320) void k_inv(float* __restrict__ out) {
    __shared__ float2 tb[128];
    __shared__ float2 Pa[17 * NKY];
    __shared__ float2 Ma[17 * NKY];
    __shared__ float2 Zev[128][10];     // even ky j=0..8 (pad 10 -> 80B rows)
    __shared__ float2 Zod[128][8];      // odd  ky j=0..7

    const int tid = threadIdx.x;
    if (tid < 128) {
        float s, c;
        sincospif((float)tid * (2.0f / 128.0f), &s, &c);
        tb[tid] = make_float2(c, s);
    }

    const float2* Yp = g_Y + (size_t)blockIdx.x * NMODE;
    if (tid < 17 * NKY) {
        int a = tid / NKY, ky = tid - a * NKY;
        float2 yp = Yp[a * NKY + ky];
        float2 P, M;
        if (a == 0)       { P = yp; M = make_float2(0.f, 0.f); }
        else if (a == 16) { P = yp; M = yp; }
        else {
            float2 yn = Yp[(32 - a) * NKY + ky];
            P = make_float2(yp.x + yn.x, yp.y + yn.y);
            M = make_float2(yp.x - yn.x, yp.y - yn.y);
        }
        Pa[tid] = P;
        Ma[tid] = M;
    }
    __syncthreads();

    // Phase A
    if (tid < 272) {
        const int ky = tid % NKY;
        const int hb = tid / NKY;           // 0..15
        const int kj = ky >> 1;
        const bool odd = (ky & 1);
        float cw[4], sw[4], tc[4], ts[4];
        float C1[4], C2[4], S1[4], S2[4];
        #pragma unroll
        for (int j = 0; j < 4; j++) {
            int h = hb + 16 * j;
            sincospif((float)h * (1.0f / 64.0f), &sw[j], &cw[j]);
            tc[j] = 1.f; ts[j] = 0.f;
            C1[j] = 0.f; C2[j] = 0.f; S1[j] = 0.f; S2[j] = 0.f;
        }
        #pragma unroll
        for (int a = 0; a < NKY; a++) {
            float2 P = Pa[a * NKY + ky];
            float2 M = Ma[a * NKY + ky];
            #pragma unroll
            for (int j = 0; j < 4; j++) {
                C1[j] = fmaf(tc[j], P.x, C1[j]);
                C2[j] = fmaf(tc[j], P.y, C2[j]);
                S1[j] = fmaf(ts[j], M.x, S1[j]);
                S2[j] = fmaf(ts[j], M.y, S2[j]);
                float nc = fmaf(tc[j], cw[j], -ts[j] * sw[j]);
                ts[j] = fmaf(tc[j], sw[j],  ts[j] * cw[j]);
                tc[j] = nc;
            }
        }
        #pragma unroll
        for (int j = 0; j < 4; j++) {
            int h = hb + 16 * j;
            float2 zf = make_float2(C1[j] - S2[j], C2[j] + S1[j]);
            float2 zm = make_float2(C1[j] + S2[j], C2[j] - S1[j]);
            if (odd) {
                Zod[h][kj] = zf;
                if (h >= 1) Zod[128 - h][kj] = zm;
            } else {
                Zev[h][kj] = zf;
                if (h >= 1) Zev[128 - h][kj] = zm;
            }
        }
    } else if (tid < 289) {
        const int ky = tid - 272;           // h = 64: cos(pi a)=(-1)^a, sin=0
        float C1 = 0.f, C2 = 0.f;
        #pragma unroll
        for (int a = 0; a < NKY; a++) {
            float2 P = Pa[a * NKY + ky];
            float sg = (a & 1) ? -1.f : 1.f;
            C1 = fmaf(sg, P.x, C1);
            C2 = fmaf(sg, P.y, C2);
        }
        if (ky & 1) Zod[64][ky >> 1] = make_float2(C1, C2);
        else        Zev[64][ky >> 1] = make_float2(C1, C2);
    }
    __syncthreads();

    // Phase B
    if (tid < 256) {
        const int w  = tid & 31;
        const int h0 = (tid >> 5) * 16;
        float ck[NKY], sk[NKY];
        #pragma unroll
        for (int ky = 0; ky < NKY; ky++) {
            float2 t = tb[(ky * w) & 127];
            float a = ky ? 2.0f : 1.0f;
            ck[ky] = a * t.x;
            sk[ky] = a * t.y;
        }

        float* op = out + (size_t)blockIdx.x * 16384;
        for (int h = h0; h < h0 + 16; h++) {
            float4 e01 = *(const float4*)&Zev[h][0];
            float4 e23 = *(const float4*)&Zev[h][2];
            float4 e45 = *(const float4*)&Zev[h][4];
            float4 e67 = *(const float4*)&Zev[h][6];
            float2 e8  = Zev[h][8];
            float4 o01 = *(const float4*)&Zod[h][0];
            float4 o23 = *(const float4*)&Zod[h][2];
            float4 o45 = *(const float4*)&Zod[h][4];
            float4 o67 = *(const float4*)&Zod[h][6];

            float Ce = ck[0] * e01.x;          float Se = sk[0] * e01.y;
            Ce = fmaf(ck[2],  e01.z, Ce);      Se = fmaf(sk[2],  e01.w, Se);
            Ce = fmaf(ck[4],  e23.x, Ce);      Se = fmaf(sk[4],  e23.y, Se);
            Ce = fmaf(ck[6],  e23.z, Ce);      Se = fmaf(sk[6],  e23.w, Se);
            Ce = fmaf(ck[8],  e45.x, Ce);      Se = fmaf(sk[8],  e45.y, Se);
            Ce = fmaf(ck[10], e45.z, Ce);      Se = fmaf(sk[10], e45.w, Se);
            Ce = fmaf(ck[12], e67.x, Ce);      Se = fmaf(sk[12], e67.y, Se);
            Ce = fmaf(ck[14], e67.z, Ce);      Se = fmaf(sk[14], e67.w, Se);
            Ce = fmaf(ck[16], e8.x,  Ce);      Se = fmaf(sk[16], e8.y,  Se);

            float Co = ck[1] * o01.x;          float So = sk[1] * o01.y;
            Co = fmaf(ck[3],  o01.z, Co);      So = fmaf(sk[3],  o01.w, So);
            Co = fmaf(ck[5],  o23.x, Co);      So = fmaf(sk[5],  o23.y, So);
            Co = fmaf(ck[7],  o23.z, Co);      So = fmaf(sk[7],  o23.w, So);
            Co = fmaf(ck[9],  o45.x, Co);      So = fmaf(sk[9],  o45.y, So);
            Co = fmaf(ck[11], o45.z, Co);      So = fmaf(sk[11], o45.w, So);
            Co = fmaf(ck[13], o67.x, Co);      So = fmaf(sk[13], o67.y, So);
            Co = fmaf(ck[15], o67.z, Co);      So = fmaf(sk[15], o67.w, So);

            float Cp = Ce + Co, Cm = Ce - Co;
            float Sp = Se + So, Sm = Se - So;
            float* oph = op + h * 128;
            oph[w] = Cp - Sp;
            if (w) {
                oph[128 - w] = Cp + Sp;
                oph[64 - w]  = Cm + Sm;
                oph[64 + w]  = Cm - Sm;
            } else {
                oph[64] = Cm;
                // w = 32 / 96 (self-paired under w<->64-w):
                float C32 = e01.x;
                C32 = fmaf(-2.f, e01.z, C32);
                C32 = fmaf( 2.f, e23.x, C32);
                C32 = fmaf(-2.f, e23.z, C32);
                C32 = fmaf( 2.f, e45.x, C32);
                C32 = fmaf(-2.f, e45.z, C32);
                C32 = fmaf( 2.f, e67.x, C32);
                C32 = fmaf(-2.f, e67.z, C32);
                C32 = fmaf( 2.f, e8.x,  C32);
                float S32 = o01.y - o01.w + o23.y - o23.w
                          + o45.y - o45.w + o67.y - o67.w;
                S32 *= 2.f;
                oph[32] = C32 - S32;
                oph[96] = C32 + S32;
            }
        }
    }
}

extern "C" void kernel_launch(void* const* d_in, const int* in_sizes, int n_in,
                              void* d_out, int out_size) {
    const float* X  = (const float*)d_in[0];
    const float* re = (const float*)d_in[1];
    const float* im = (const float*)d_in[2];
    float* out = (float*)d_out;

    const int smem_fwd = 64 * 16 + (32 * 10 + 32 * 8 + 128 * NKY) * 8
                       + 4 * (64 * 33) * 4;   // 56832 B
    cudaFuncSetAttribute(k_fwd, cudaFuncAttributeMaxDynamicSharedMemorySize, smem_fwd);

    k_fwd<<<NSLICE, 320, smem_fwd>>>(X);
    k_mix<<<dim3(17, 16), 256>>>(re, im);
    k_inv<<<NSLICE, 320>>>(out);
}

// round 13
// speedup vs baseline: 1.2755x; 1.1229x over previous
#include <cuda_runtime.h>

// OrbitalSpectralConv: B=8, C=128, H=W=128; kept modes: 32 kx rows x 17 ky cols.
// kx rows: mk 0..16 -> kx = mk; mk 17..31 -> kx = mk+96 == -(32-mk) mod 128.
#define NKY   17
#define NMODE 544           // 32*17
#define NSLICE 1024         // B*C

// Scratch (allocation banned -> device globals).
__device__ float2 g_Xf[128 * NMODE * 8];         // 4.45 MB  [c][m][b]
__device__ float2 g_Y [NSLICE * NMODE];          // 4.45 MB  [b][c][m]  (ct 0..63)
__device__ float2 g_Y2[NSLICE * NMODE];          // 4.45 MB  [b][c][m]  (ct 64..127)

// ===========================================================================
// Fused forward per (b,c) slice. 320 threads, 56832 B dynamic smem.
// Phase A (w-DFT, DOUBLE-folded, 256 threads = 64 h x 4 ky-groups):
//   even ky=2j: re = Sp0+Sp64+(-1)^j Sp32 + sum_{w=1..31} Ae[w] cos; im = -sum Be sin
//   odd  ky=2j+1: re = Sp0-Sp64 + sum Ao cos; im = -(-1)^j Sm32 - sum Bo sin
//   Q[h][w] = (Ae, Ao, Be, Bo); Ae/Ao = Sp[w]+/-Sp[64-w]; Be/Bo = Sm[w]-/+Sm[64-w];
//   Sp[w]=x[w]+x[128-w], Sm[w]=x[w]-x[128-w].      -> Gs[h][ky] in smem
// Phase B (h-DFT, folded, rotation trig, 289 threads = (a,ky)):
//   Xf[+a]=(C1+S2, C2-S1), Xf[-a]=(C1-S2, C2+S1), scaled 1/16384 -> g_Xf[c][m][b]
// ===========================================================================
__global__ __launch_bounds__(320) void k_fwd(const float* __restrict__ X) {
    extern __shared__ char smraw[];
    float4* Bd = (float4*)smraw;                 // [64]   (Sp0, Sp64, Sp32, Sm32)
    float2* Te = (float2*)(Bd + 64);             // [32][10] cos/sin(2pi*2j*w/128)
    float2* To = Te + 32 * 10;                   // [32][8]  cos/sin(2pi*(2j+1)*w/128)
    float2* Gs = To + 32 * 8;                    // [128][17]
    float4* Q  = (float4*)(Gs + 128 * NKY);      // [64][33]  (Ae, Ao, Be, Bo)

    const int tid = threadIdx.x;

    if (tid < 320) {
        int w = tid / 10, j = tid - (tid / 10) * 10;
        float s, c;
        sincospif((float)((w * 2 * j) & 127) * (2.0f / 128.0f), &s, &c);
        Te[tid] = make_float2(c, s);
    }
    if (tid < 256) {
        int w = tid >> 3, j = tid & 7;
        float s, c;
        sincospif((float)((w * (2 * j + 1)) & 127) * (2.0f / 128.0f), &s, &c);
        To[tid] = make_float2(c, s);
    }

    const float* Xp = X + (size_t)blockIdx.x * 16384;

    const int hl  = tid & 63;
    const int grp = tid >> 6;

    for (int half = 0; half < 2; half++) {
        __syncthreads();    // covers trig init (1st) and Q/Bd reuse (2nd)
        for (int i = tid; i < 2048; i += 320) {
            int hr = i >> 5, w = i & 31;
            const float* row = Xp + (half * 64 + hr) * 128;
            if (w == 0) {
                float x0 = row[0], x64 = row[64], x32 = row[32], x96 = row[96];
                Bd[hr] = make_float4(x0, x64, x32 + x96, x32 - x96);
            } else {
                float xa = row[w], xb = row[64 - w], xc = row[64 + w], xd = row[128 - w];
                float sp  = xa + xd, sm  = xa - xd;
                float spb = xb + xc, smb = xb - xc;
                Q[hr * 33 + w] = make_float4(sp + spb, sp - spb, sm - smb, sm + smb);
            }
        }
        __syncthreads();

        if (grp < 4) {
            const float4 bd = Bd[hl];
            const int h = half * 64 + hl;
            const float4* Qr = Q + hl * 33;

            if (grp == 0) {                       // even ky 0,2,4,6,8
                float gr[5], gi[5];
                #pragma unroll
                for (int j = 0; j < 5; j++) {
                    gr[j] = bd.x + bd.y + ((j & 1) ? -bd.z : bd.z);
                    gi[j] = 0.f;
                }
                #pragma unroll 4
                for (int w = 1; w < 32; w++) {
                    float4 q = Qr[w];
                    float a  = q.x;
                    float nb = -q.z;
                    float4 t01 = *(const float4*)(Te + w * 10);
                    float4 t23 = *(const float4*)(Te + w * 10 + 2);
                    float2 t4  = Te[w * 10 + 4];
                    gr[0]=fmaf(t01.x,a,gr[0]); gi[0]=fmaf(t01.y,nb,gi[0]);
                    gr[1]=fmaf(t01.z,a,gr[1]); gi[1]=fmaf(t01.w,nb,gi[1]);
                    gr[2]=fmaf(t23.x,a,gr[2]); gi[2]=fmaf(t23.y,nb,gi[2]);
                    gr[3]=fmaf(t23.z,a,gr[3]); gi[3]=fmaf(t23.w,nb,gi[3]);
                    gr[4]=fmaf(t4.x ,a,gr[4]); gi[4]=fmaf(t4.y ,nb,gi[4]);
                }
                #pragma unroll
                for (int j = 0; j < 5; j++)
                    Gs[h * NKY + 2 * j] = make_float2(gr[j], gi[j]);
            } else if (grp == 1) {                // even ky 10,12,14,16 (j=5..8)
                float gr[4], gi[4];
                #pragma unroll
                for (int j = 0; j < 4; j++) {
                    int jj = 5 + j;
                    gr[j] = bd.x + bd.y + ((jj & 1) ? -bd.z : bd.z);
                    gi[j] = 0.f;
                }
                #pragma unroll 4
                for (int w = 1; w < 32; w++) {
                    float4 q = Qr[w];
                    float a  = q.x;
                    float nb = -q.z;
                    float2 t5  = Te[w * 10 + 5];
                    float4 t67 = *(const float4*)(Te + w * 10 + 6);
                    float2 t8  = Te[w * 10 + 8];
                    gr[0]=fmaf(t5.x ,a,gr[0]); gi[0]=fmaf(t5.y ,nb,gi[0]);
                    gr[1]=fmaf(t67.x,a,gr[1]); gi[1]=fmaf(t67.y,nb,gi[1]);
                    gr[2]=fmaf(t67.z,a,gr[2]); gi[2]=fmaf(t67.w,nb,gi[2]);
                    gr[3]=fmaf(t8.x ,a,gr[3]); gi[3]=fmaf(t8.y ,nb,gi[3]);
                }
                #pragma unroll
                for (int j = 0; j < 4; j++)
                    Gs[h * NKY + 10 + 2 * j] = make_float2(gr[j], gi[j]);
            } else if (grp == 2) {                // odd ky 1,3,5,7 (j=0..3)
                float gr[4], gi[4];
                #pragma unroll
                for (int j = 0; j < 4; j++) {
                    gr[j] = bd.x - bd.y;
                    gi[j] = (j & 1) ? bd.w : -bd.w;
                }
                #pragma unroll 4
                for (int w = 1; w < 32; w++) {
                    float4 q = Qr[w];
                    float a  = q.y;
                    float nb = -q.w;
                    float4 t01 = *(const float4*)(To + w * 8);
                    float4 t23 = *(const float4*)(To + w * 8 + 2);
                    gr[0]=fmaf(t01.x,a,gr[0]); gi[0]=fmaf(t01.y,nb,gi[0]);
                    gr[1]=fmaf(t01.z,a,gr[1]); gi[1]=fmaf(t01.w,nb,gi[1]);
                    gr[2]=fmaf(t23.x,a,gr[2]); gi[2]=fmaf(t23.y,nb,gi[2]);
                    gr[3]=fmaf(t23.z,a,gr[3]); gi[3]=fmaf(t23.w,nb,gi[3]);
                }
                #pragma unroll
                for (int j = 0; j < 4; j++)
                    Gs[h * NKY + 2 * j + 1] = make_float2(gr[j], gi[j]);
            } else {                              // odd ky 9,11,13,15 (j=4..7)
                float gr[4], gi[4];
                #pragma unroll
                for (int j = 0; j < 4; j++) {
                    int jj = 4 + j;
                    gr[j] = bd.x - bd.y;
                    gi[j] = (jj & 1) ? bd.w : -bd.w;
                }
                #pragma unroll 4
                for (int w = 1; w < 32; w++) {
                    float4 q = Qr[w];
                    float a  = q.y;
                    float nb = -q.w;
                    float4 t45 = *(const float4*)(To + w * 8 + 4);
                    float4 t67 = *(const float4*)(To + w * 8 + 6);
                    gr[0]=fmaf(t45.x,a,gr[0]); gi[0]=fmaf(t45.y,nb,gi[0]);
                    gr[1]=fmaf(t45.z,a,gr[1]); gi[1]=fmaf(t45.w,nb,gi[1]);
                    gr[2]=fmaf(t67.x,a,gr[2]); gi[2]=fmaf(t67.y,nb,gi[2]);
                    gr[3]=fmaf(t67.z,a,gr[3]); gi[3]=fmaf(t67.w,nb,gi[3]);
                }
                #pragma unroll
                for (int j = 0; j < 4; j++)
                    Gs[h * NKY + 9 + 2 * j] = make_float2(gr[j], gi[j]);
            }
        }
    }
    __syncthreads();

    // Phase B: h-DFT, folded, rotation trig.
    if (tid < 17 * NKY) {
        const int a = tid / NKY, ky = tid - a * NKY;
        float cw, sw;
        sincospif((float)a * (1.0f / 64.0f), &sw, &cw);   // e^{i 2pi a/128}

        float2 g0  = Gs[0 * NKY + ky];
        float2 g64 = Gs[64 * NKY + ky];
        const float sgn = (a & 1) ? -1.f : 1.f;
        float C1 = g0.x + sgn * g64.x;
        float C2 = g0.y + sgn * g64.y;
        float S1 = 0.f, S2 = 0.f;

        float tc = cw, ts = sw;
        #pragma unroll 3
        for (int h = 1; h < 64; h++) {
            float2 ga = Gs[h * NKY + ky];
            float2 gb = Gs[(128 - h) * NKY + ky];
            float pr = ga.x + gb.x, pi = ga.y + gb.y;
            float mr = ga.x - gb.x, mi = ga.y - gb.y;
            C1 = fmaf(tc, pr, C1);
            C2 = fmaf(tc, pi, C2);
            S1 = fmaf(ts, mr, S1);
            S2 = fmaf(ts, mi, S2);
            float nc = fmaf(tc, cw, -ts * sw);
            ts = fmaf(tc, sw,  ts * cw);
            tc = nc;
        }

        const float inv = 1.0f / 16384.0f;
        const int b = blockIdx.x >> 7, c = blockIdx.x & 127;
        float2* Xfb = g_Xf + (size_t)c * (NMODE * 8) + b;
        Xfb[(a * NKY + ky) * 8] = make_float2((C1 + S2) * inv, (C2 - S1) * inv);
        if (a >= 1 && a <= 15)
            Xfb[((32 - a) * NKY + ky) * 8] =
                make_float2((C1 - S2) * inv, (C2 + S1) * inv);
    }
}

// ===========================================================================
// Kernel 2: spectral channel mix, skew-Hermitian weight built on the fly.
//   Y[b,c,m] = sum_ct [(re[c,ct,m]-re[ct,c,m]) + i(im[c,ct,m]+im[ct,c,m])] Xf[b,ct,m]
// grid (17 m-tiles x 16 c-tiles x 2 ct-halves); z=0 -> g_Y, z=1 -> g_Y2
// (summed in k_inv). Doubles resident warps to hide DRAM latency.
// ===========================================================================
__global__ __launch_bounds__(256) void k_mix(const float* __restrict__ re,
                                             const float* __restrict__ im) {
    const int mi  = threadIdx.x & 31;
    const int ci  = threadIdx.x >> 5;
    const int m   = blockIdx.x * 32 + mi;
    const int c   = blockIdx.y * 8 + ci;
    const int ct0 = blockIdx.z * 64;

    float yr[8], yi[8];
    #pragma unroll
    for (int b = 0; b < 8; b++) { yr[b] = 0.f; yi[b] = 0.f; }

    const float* reA = re + (size_t)c * (128 * NMODE) + m;   // [c][ct][m]
    const float* reB = re + (size_t)c * NMODE + m;           // [ct][c][m]
    const float* imA = im + (size_t)c * (128 * NMODE) + m;
    const float* imB = im + (size_t)c * NMODE + m;
    const float4* xb = (const float4*)g_Xf + (size_t)m * 4;  // [ct][m][b0..7]

    #pragma unroll 4
    for (int ct = ct0; ct < ct0 + 64; ct++) {
        float wre = reA[ct * NMODE] - reB[ct * (128 * NMODE)];
        float wim = imA[ct * NMODE] + imB[ct * (128 * NMODE)];
        const float4* x4 = xb + (size_t)ct * (NMODE * 4);
        float4 x0 = x4[0], x1 = x4[1], x2 = x4[2], x3 = x4[3];
        yr[0]=fmaf(wre,x0.x,fmaf(-wim,x0.y,yr[0])); yi[0]=fmaf(wre,x0.y,fmaf(wim,x0.x,yi[0]));
        yr[1]=fmaf(wre,x0.z,fmaf(-wim,x0.w,yr[1])); yi[1]=fmaf(wre,x0.w,fmaf(wim,x0.z,yi[1]));
        yr[2]=fmaf(wre,x1.x,fmaf(-wim,x1.y,yr[2])); yi[2]=fmaf(wre,x1.y,fmaf(wim,x1.x,yi[2]));
        yr[3]=fmaf(wre,x1.z,fmaf(-wim,x1.w,yr[3])); yi[3]=fmaf(wre,x1.w,fmaf(wim,x1.z,yi[3]));
        yr[4]=fmaf(wre,x2.x,fmaf(-wim,x2.y,yr[4])); yi[4]=fmaf(wre,x2.y,fmaf(wim,x2.x,yi[4]));
        yr[5]=fmaf(wre,x2.z,fmaf(-wim,x2.w,yr[5])); yi[5]=fmaf(wre,x2.w,fmaf(wim,x2.z,yi[5]));
        yr[6]=fmaf(wre,x3.x,fmaf(-wim,x3.y,yr[6])); yi[6]=fmaf(wre,x3.y,fmaf(wim,x3.x,yi[6]));
        yr[7]=fmaf(wre,x3.z,fmaf(-wim,x3.w,yr[7])); yi[7]=fmaf(wre,x3.w,fmaf(wim,x3.z,yi[7]));
    }
    float2* outY = blockIdx.z ? g_Y2 : g_Y;
    #pragma unroll
    for (int b = 0; b < 8; b++)
        outY[(size_t)(b * 128 + c) * NMODE + m] = make_float2(yr[b], yi[b]);
}

// ===========================================================================
// Fused inverse per (b,c) slice. 320 threads.
// Phase A (kx->h, folded, rotation trig): P/M built from g_Y + g_Y2;
//   Z[h]=(C1-S2, C2+S1), Z[128-h]=(C1+S2, C2-S1)  -> Zev/Zod (ky parity-split)
// Phase B (ky->w c2r, QUARTER-folded, 256 threads): thread (h, w<=31) emits
//   out[w], out[128-w], out[64-w], out[64+w]; w=0 thread also emits 32/96.
// ===========================================================================
__global__ __launch_bounds__(320) void k_inv(float* __restrict__ out) {
    __shared__ float2 tb[128];
    __shared__ float2 Pa[17 * NKY];
    __shared__ float2 Ma[17 * NKY];
    __shared__ float2 Zev[128][10];     // even ky j=0..8 (pad 10 -> 80B rows)
    __shared__ float2 Zod[128][8];      // odd  ky j=0..7

    const int tid = threadIdx.x;
    if (tid < 128) {
        float s, c;
        sincospif((float)tid * (2.0f / 128.0f), &s, &c);
        tb[tid] = make_float2(c, s);
    }

    const float2* Yp  = g_Y  + (size_t)blockIdx.x * NMODE;
    const float2* Yp2 = g_Y2 + (size_t)blockIdx.x * NMODE;
    if (tid < 17 * NKY) {
        int a = tid / NKY, ky = tid - a * NKY;
        float2 ya = Yp[a * NKY + ky], yb = Yp2[a * NKY + ky];
        float2 yp = make_float2(ya.x + yb.x, ya.y + yb.y);
        float2 P, M;
        if (a == 0)       { P = yp; M = make_float2(0.f, 0.f); }
        else if (a == 16) { P = yp; M = yp; }
        else {
            float2 na = Yp[(32 - a) * NKY + ky], nb = Yp2[(32 - a) * NKY + ky];
            float2 yn = make_float2(na.x + nb.x, na.y + nb.y);
            P = make_float2(yp.x + yn.x, yp.y + yn.y);
            M = make_float2(yp.x - yn.x, yp.y - yn.y);
        }
        Pa[tid] = P;
        Ma[tid] = M;
    }
    __syncthreads();

    // Phase A
    if (tid < 272) {
        const int ky = tid % NKY;
        const int hb = tid / NKY;           // 0..15
        const int kj = ky >> 1;
        const bool odd = (ky & 1);
        float cw[4], sw[4], tc[4], ts[4];
        float C1[4], C2[4], S1[4], S2[4];
        #pragma unroll
        for (int j = 0; j < 4; j++) {
            int h = hb + 16 * j;
            sincospif((float)h * (1.0f / 64.0f), &sw[j], &cw[j]);
            tc[j] = 1.f; ts[j] = 0.f;
            C1[j] = 0.f; C2[j] = 0.f; S1[j] = 0.f; S2[j] = 0.f;
        }
        #pragma unroll
        for (int a = 0; a < NKY; a++) {
            float2 P = Pa[a * NKY + ky];
            float2 M = Ma[a * NKY + ky];
            #pragma unroll
            for (int j = 0; j < 4; j++) {
                C1[j] = fmaf(tc[j], P.x, C1[j]);
                C2[j] = fmaf(tc[j], P.y, C2[j]);
                S1[j] = fmaf(ts[j], M.x, S1[j]);
                S2[j] = fmaf(ts[j], M.y, S2[j]);
                float nc = fmaf(tc[j], cw[j], -ts[j] * sw[j]);
                ts[j] = fmaf(tc[j], sw[j],  ts[j] * cw[j]);
                tc[j] = nc;
            }
        }
        #pragma unroll
        for (int j = 0; j < 4; j++) {
            int h = hb + 16 * j;
            float2 zf = make_float2(C1[j] - S2[j], C2[j] + S1[j]);
            float2 zm = make_float2(C1[j] + S2[j], C2[j] - S1[j]);
            if (odd) {
                Zod[h][kj] = zf;
                if (h >= 1) Zod[128 - h][kj] = zm;
            } else {
                Zev[h][kj] = zf;
                if (h >= 1) Zev[128 - h][kj] = zm;
            }
        }
    } else if (tid < 289) {
        const int ky = tid - 272;           // h = 64: cos(pi a)=(-1)^a, sin=0
        float C1 = 0.f, C2 = 0.f;
        #pragma unroll
        for (int a = 0; a < NKY; a++) {
            float2 P = Pa[a * NKY + ky];
            float sg = (a & 1) ? -1.f : 1.f;
            C1 = fmaf(sg, P.x, C1);
            C2 = fmaf(sg, P.y, C2);
        }
        if (ky & 1) Zod[64][ky >> 1] = make_float2(C1, C2);
        else        Zev[64][ky >> 1] = make_float2(C1, C2);
    }
    __syncthreads();

    // Phase B
    if (tid < 256) {
        const int w  = tid & 31;
        const int h0 = (tid >> 5) * 16;
        float ck[NKY], sk[NKY];
        #pragma unroll
        for (int ky = 0; ky < NKY; ky++) {
            float2 t = tb[(ky * w) & 127];
            float a = ky ? 2.0f : 1.0f;
            ck[ky] = a * t.x;
            sk[ky] = a * t.y;
        }

        float* op = out + (size_t)blockIdx.x * 16384;
        for (int h = h0; h < h0 + 16; h++) {
            float4 e01 = *(const float4*)&Zev[h][0];
            float4 e23 = *(const float4*)&Zev[h][2];
            float4 e45 = *(const float4*)&Zev[h][4];
            float4 e67 = *(const float4*)&Zev[h][6];
            float2 e8  = Zev[h][8];
            float4 o01 = *(const float4*)&Zod[h][0];
            float4 o23 = *(const float4*)&Zod[h][2];
            float4 o45 = *(const float4*)&Zod[h][4];
            float4 o67 = *(const float4*)&Zod[h][6];

            float Ce = ck[0] * e01.x;          float Se = sk[0] * e01.y;
            Ce = fmaf(ck[2],  e01.z, Ce);      Se = fmaf(sk[2],  e01.w, Se);
            Ce = fmaf(ck[4],  e23.x, Ce);      Se = fmaf(sk[4],  e23.y, Se);
            Ce = fmaf(ck[6],  e23.z, Ce);      Se = fmaf(sk[6],  e23.w, Se);
            Ce = fmaf(ck[8],  e45.x, Ce);      Se = fmaf(sk[8],  e45.y, Se);
            Ce = fmaf(ck[10], e45.z, Ce);      Se = fmaf(sk[10], e45.w, Se);
            Ce = fmaf(ck[12], e67.x, Ce);      Se = fmaf(sk[12], e67.y, Se);
            Ce = fmaf(ck[14], e67.z, Ce);      Se = fmaf(sk[14], e67.w, Se);
            Ce = fmaf(ck[16], e8.x,  Ce);      Se = fmaf(sk[16], e8.y,  Se);

            float Co = ck[1] * o01.x;          float So = sk[1] * o01.y;
            Co = fmaf(ck[3],  o01.z, Co);      So = fmaf(sk[3],  o01.w, So);
            Co = fmaf(ck[5],  o23.x, Co);      So = fmaf(sk[5],  o23.y, So);
            Co = fmaf(ck[7],  o23.z, Co);      So = fmaf(sk[7],  o23.w, So);
            Co = fmaf(ck[9],  o45.x, Co);      So = fmaf(sk[9],  o45.y, So);
            Co = fmaf(ck[11], o45.z, Co);      So = fmaf(sk[11], o45.w, So);
            Co = fmaf(ck[13], o67.x, Co);      So = fmaf(sk[13], o67.y, So);
            Co = fmaf(ck[15], o67.z, Co);      So = fmaf(sk[15], o67.w, So);

            float Cp = Ce + Co, Cm = Ce - Co;
            float Sp = Se + So, Sm = Se - So;
            float* oph = op + h * 128;
            oph[w] = Cp - Sp;
            if (w) {
                oph[128 - w] = Cp + Sp;
                oph[64 - w]  = Cm + Sm;
                oph[64 + w]  = Cm - Sm;
            } else {
                oph[64] = Cm;
                // w = 32 / 96 (self-paired under w<->64-w):
                float C32 = e01.x;
                C32 = fmaf(-2.f, e01.z, C32);
                C32 = fmaf( 2.f, e23.x, C32);
                C32 = fmaf(-2.f, e23.z, C32);
                C32 = fmaf( 2.f, e45.x, C32);
                C32 = fmaf(-2.f, e45.z, C32);
                C32 = fmaf( 2.f, e67.x, C32);
                C32 = fmaf(-2.f, e67.z, C32);
                C32 = fmaf( 2.f, e8.x,  C32);
                float S32 = o01.y - o01.w + o23.y - o23.w
                          + o45.y - o45.w + o67.y - o67.w;
                S32 *= 2.f;
                oph[32] = C32 - S32;
                oph[96] = C32 + S32;
            }
        }
    }
}

extern "C" void kernel_launch(void* const* d_in, const int* in_sizes, int n_in,
                              void* d_out, int out_size) {
    const float* X  = (const float*)d_in[0];
    const float* re = (const float*)d_in[1];
    const float* im = (const float*)d_in[2];
    float* out = (float*)d_out;

    const int smem_fwd = 64 * 16 + (32 * 10 + 32 * 8 + 128 * NKY) * 8
                       + (64 * 33) * 16;   // 56832 B
    cudaFuncSetAttribute(k_fwd, cudaFuncAttributeMaxDynamicSharedMemorySize, smem_fwd);

    k_fwd<<<NSLICE, 320, smem_fwd>>>(X);
    k_mix<<<dim3(17, 16, 2), 256>>>(re, im);
    k_inv<<<NSLICE, 320>>>(out);
}

// round 14
// speedup vs baseline: 1.5032x; 1.1786x over previous
#include <cuda_runtime.h>

// OrbitalSpectralConv: B=8, C=128, H=W=128; kept modes: 32 kx rows x 17 ky cols.
// kx rows: mk 0..16 -> kx = mk; mk 17..31 -> kx = mk+96 == -(32-mk) mod 128.
#define NKY   17
#define NMODE 544           // 32*17
#define NSLICE 1024         // B*C

// Scratch (allocation banned -> device globals).
__device__ float2 g_Xf[128 * NMODE * 8];         // 4.45 MB  [ct][m][b]
__device__ float2 g_Y [NSLICE * NMODE];          // 4.45 MB  [b][c][m]  (ct 0..63)
__device__ float2 g_Y2[NSLICE * NMODE];          // 4.45 MB  [b][c][m]  (ct 64..127)

// ===========================================================================
// Fused forward per (b,c) slice. 320 threads, 56832 B dynamic smem.
// Phase A (w-DFT, DOUBLE-folded, 256 threads = 64 h x 4 ky-groups):
//   even ky=2j: re = Sp0+Sp64+(-1)^j Sp32 + sum_{w=1..31} Ae[w] cos; im = -sum Be sin
//   odd  ky=2j+1: re = Sp0-Sp64 + sum Ao cos; im = -(-1)^j Sm32 - sum Bo sin
//   QE[h][w]=(Ae,Be), QO[h][w]=(Ao,Bo); Ae/Ao = Sp[w]+/-Sp[64-w];
//   Be/Bo = Sm[w]-/+Sm[64-w]; Sp[w]=x[w]+x[128-w], Sm[w]=x[w]-x[128-w].
// Phase B (h-DFT, folded, rotation trig, 289 threads = (a,ky)):
//   Xf[+a]=(C1+S2, C2-S1), Xf[-a]=(C1-S2, C2+S1), scaled 1/16384 -> g_Xf[c][m][b]
// ===========================================================================
__global__ __launch_bounds__(320) void k_fwd(const float* __restrict__ X) {
    extern __shared__ char smraw[];
    float4* Bd = (float4*)smraw;                 // [64]   (Sp0, Sp64, Sp32, Sm32)
    float2* Te = (float2*)(Bd + 64);             // [32][10] cos/sin(2pi*2j*w/128)
    float2* To = Te + 32 * 10;                   // [32][8]  cos/sin(2pi*(2j+1)*w/128)
    float2* Gs = To + 32 * 8;                    // [128][17]
    float2* QE = Gs + 128 * NKY;                 // [64][33]  (Ae, Be)
    float2* QO = QE + 64 * 33;                   // [64][33]  (Ao, Bo)

    const int tid = threadIdx.x;

    if (tid < 320) {
        int w = tid / 10, j = tid - (tid / 10) * 10;
        float s, c;
        sincospif((float)((w * 2 * j) & 127) * (2.0f / 128.0f), &s, &c);
        Te[tid] = make_float2(c, s);
    }
    if (tid < 256) {
        int w = tid >> 3, j = tid & 7;
        float s, c;
        sincospif((float)((w * (2 * j + 1)) & 127) * (2.0f / 128.0f), &s, &c);
        To[tid] = make_float2(c, s);
    }

    const float* Xp = X + (size_t)blockIdx.x * 16384;

    const int hl  = tid & 63;
    const int grp = tid >> 6;

    for (int half = 0; half < 2; half++) {
        __syncthreads();    // covers trig init (1st) and QE/QO/Bd reuse (2nd)
        for (int i = tid; i < 2048; i += 320) {
            int hr = i >> 5, w = i & 31;
            const float* row = Xp + (half * 64 + hr) * 128;
            if (w == 0) {
                float x0 = row[0], x64 = row[64], x32 = row[32], x96 = row[96];
                Bd[hr] = make_float4(x0, x64, x32 + x96, x32 - x96);
            } else {
                float xa = row[w], xb = row[64 - w], xc = row[64 + w], xd = row[128 - w];
                float sp  = xa + xd, sm  = xa - xd;
                float spb = xb + xc, smb = xb - xc;
                QE[hr * 33 + w] = make_float2(sp + spb, sm - smb);
                QO[hr * 33 + w] = make_float2(sp - spb, sm + smb);
            }
        }
        __syncthreads();

        if (grp < 4) {
            const float4 bd = Bd[hl];
            const int h = half * 64 + hl;
            const float2* Qr = (grp < 2 ? QE : QO) + hl * 33;

            if (grp == 0) {                       // even ky 0,2,4,6,8
                float gr[5], gi[5];
                #pragma unroll
                for (int j = 0; j < 5; j++) {
                    gr[j] = bd.x + bd.y + ((j & 1) ? -bd.z : bd.z);
                    gi[j] = 0.f;
                }
                #pragma unroll 4
                for (int w = 1; w < 32; w++) {
                    float2 q = Qr[w];
                    float a  = q.x;
                    float nb = -q.y;
                    float4 t01 = *(const float4*)(Te + w * 10);
                    float4 t23 = *(const float4*)(Te + w * 10 + 2);
                    float2 t4  = Te[w * 10 + 4];
                    gr[0]=fmaf(t01.x,a,gr[0]); gi[0]=fmaf(t01.y,nb,gi[0]);
                    gr[1]=fmaf(t01.z,a,gr[1]); gi[1]=fmaf(t01.w,nb,gi[1]);
                    gr[2]=fmaf(t23.x,a,gr[2]); gi[2]=fmaf(t23.y,nb,gi[2]);
                    gr[3]=fmaf(t23.z,a,gr[3]); gi[3]=fmaf(t23.w,nb,gi[3]);
                    gr[4]=fmaf(t4.x ,a,gr[4]); gi[4]=fmaf(t4.y ,nb,gi[4]);
                }
                #pragma unroll
                for (int j = 0; j < 5; j++)
                    Gs[h * NKY + 2 * j] = make_float2(gr[j], gi[j]);
            } else if (grp == 1) {                // even ky 10,12,14,16 (j=5..8)
                float gr[4], gi[4];
                #pragma unroll
                for (int j = 0; j < 4; j++) {
                    int jj = 5 + j;
                    gr[j] = bd.x + bd.y + ((jj & 1) ? -bd.z : bd.z);
                    gi[j] = 0.f;
                }
                #pragma unroll 4
                for (int w = 1; w < 32; w++) {
                    float2 q = Qr[w];
                    float a  = q.x;
                    float nb = -q.y;
                    float2 t5  = Te[w * 10 + 5];
                    float4 t67 = *(const float4*)(Te + w * 10 + 6);
                    float2 t8  = Te[w * 10 + 8];
                    gr[0]=fmaf(t5.x ,a,gr[0]); gi[0]=fmaf(t5.y ,nb,gi[0]);
                    gr[1]=fmaf(t67.x,a,gr[1]); gi[1]=fmaf(t67.y,nb,gi[1]);
                    gr[2]=fmaf(t67.z,a,gr[2]); gi[2]=fmaf(t67.w,nb,gi[2]);
                    gr[3]=fmaf(t8.x ,a,gr[3]); gi[3]=fmaf(t8.y ,nb,gi[3]);
                }
                #pragma unroll
                for (int j = 0; j < 4; j++)
                    Gs[h * NKY + 10 + 2 * j] = make_float2(gr[j], gi[j]);
            } else if (grp == 2) {                // odd ky 1,3,5,7 (j=0..3)
                float gr[4], gi[4];
                #pragma unroll
                for (int j = 0; j < 4; j++) {
                    gr[j] = bd.x - bd.y;
                    gi[j] = (j & 1) ? bd.w : -bd.w;
                }
                #pragma unroll 4
                for (int w = 1; w < 32; w++) {
                    float2 q = Qr[w];
                    float a  = q.x;
                    float nb = -q.y;
                    float4 t01 = *(const float4*)(To + w * 8);
                    float4 t23 = *(const float4*)(To + w * 8 + 2);
                    gr[0]=fmaf(t01.x,a,gr[0]); gi[0]=fmaf(t01.y,nb,gi[0]);
                    gr[1]=fmaf(t01.z,a,gr[1]); gi[1]=fmaf(t01.w,nb,gi[1]);
                    gr[2]=fmaf(t23.x,a,gr[2]); gi[2]=fmaf(t23.y,nb,gi[2]);
                    gr[3]=fmaf(t23.z,a,gr[3]); gi[3]=fmaf(t23.w,nb,gi[3]);
                }
                #pragma unroll
                for (int j = 0; j < 4; j++)
                    Gs[h * NKY + 2 * j + 1] = make_float2(gr[j], gi[j]);
            } else {                              // odd ky 9,11,13,15 (j=4..7)
                float gr[4], gi[4];
                #pragma unroll
                for (int j = 0; j < 4; j++) {
                    int jj = 4 + j;
                    gr[j] = bd.x - bd.y;
                    gi[j] = (jj & 1) ? bd.w : -bd.w;
                }
                #pragma unroll 4
                for (int w = 1; w < 32; w++) {
                    float2 q = Qr[w];
                    float a  = q.x;
                    float nb = -q.y;
                    float4 t45 = *(const float4*)(To + w * 8 + 4);
                    float4 t67 = *(const float4*)(To + w * 8 + 6);
                    gr[0]=fmaf(t45.x,a,gr[0]); gi[0]=fmaf(t45.y,nb,gi[0]);
                    gr[1]=fmaf(t45.z,a,gr[1]); gi[1]=fmaf(t45.w,nb,gi[1]);
                    gr[2]=fmaf(t67.x,a,gr[2]); gi[2]=fmaf(t67.y,nb,gi[2]);
                    gr[3]=fmaf(t67.z,a,gr[3]); gi[3]=fmaf(t67.w,nb,gi[3]);
                }
                #pragma unroll
                for (int j = 0; j < 4; j++)
                    Gs[h * NKY + 9 + 2 * j] = make_float2(gr[j], gi[j]);
            }
        }
    }
    __syncthreads();

    // Phase B: h-DFT, folded, rotation trig.
    if (tid < 17 * NKY) {
        const int a = tid / NKY, ky = tid - a * NKY;
        float cw, sw;
        sincospif((float)a * (1.0f / 64.0f), &sw, &cw);   // e^{i 2pi a/128}

        float2 g0  = Gs[0 * NKY + ky];
        float2 g64 = Gs[64 * NKY + ky];
        const float sgn = (a & 1) ? -1.f : 1.f;
        float C1 = g0.x + sgn * g64.x;
        float C2 = g0.y + sgn * g64.y;
        float S1 = 0.f, S2 = 0.f;

        float tc = cw, ts = sw;
        #pragma unroll 3
        for (int h = 1; h < 64; h++) {
            float2 ga = Gs[h * NKY + ky];
            float2 gb = Gs[(128 - h) * NKY + ky];
            float pr = ga.x + gb.x, pi = ga.y + gb.y;
            float mr = ga.x - gb.x, mi = ga.y - gb.y;
            C1 = fmaf(tc, pr, C1);
            C2 = fmaf(tc, pi, C2);
            S1 = fmaf(ts, mr, S1);
            S2 = fmaf(ts, mi, S2);
            float nc = fmaf(tc, cw, -ts * sw);
            ts = fmaf(tc, sw,  ts * cw);
            tc = nc;
        }

        const float inv = 1.0f / 16384.0f;
        const int b = blockIdx.x >> 7, c = blockIdx.x & 127;
        float2* Xfb = g_Xf + (size_t)c * (NMODE * 8) + b;
        Xfb[(a * NKY + ky) * 8] = make_float2((C1 + S2) * inv, (C2 - S1) * inv);
        if (a >= 1 && a <= 15)
            Xfb[((32 - a) * NKY + ky) * 8] =
                make_float2((C1 - S2) * inv, (C2 + S1) * inv);
    }
}

// ===========================================================================
// Kernel 2 (v4): spectral channel mix with SMEM-tiled Xf.
//   Y[b,c,m] = sum_ct [(re[c,ct,m]-re[ct,c,m]) + i(im[c,ct,m]+im[ct,c,m])] Xf[b,ct,m]
// grid (17 m x 16 c x 2 ct-halves), block 256 = 32 m x 8 c.
// Xf chunk of 16 ct staged to smem transposed [b][ct][m] -> compute reads are
// conflict-free LDS.64; Xf L2 traffic drops 8x (c-tile reuse in smem).
// ===========================================================================
__global__ __launch_bounds__(256) void k_mix(const float* __restrict__ re,
                                             const float* __restrict__ im) {
    __shared__ float2 tile[8][16][33];   // [b][ctl][m], pad 33

    const int mi  = threadIdx.x & 31;
    const int ci  = threadIdx.x >> 5;
    const int m0  = blockIdx.x * 32;
    const int m   = m0 + mi;
    const int c   = blockIdx.y * 8 + ci;
    const int ct0 = blockIdx.z * 64;

    float yr[8], yi[8];
    #pragma unroll
    for (int b = 0; b < 8; b++) { yr[b] = 0.f; yi[b] = 0.f; }

    const float* reA = re + (size_t)c * (128 * NMODE) + m;   // [c][ct][m]
    const float* reB = re + (size_t)c * NMODE + m;           // [ct][c][m]
    const float* imA = im + (size_t)c * (128 * NMODE) + m;
    const float* imB = im + (size_t)c * NMODE + m;

    for (int chunk = 0; chunk < 64; chunk += 16) {
        __syncthreads();
        // stage 16 ct x 32 m x 8 b of Xf (2048 float4), transposing to [b][ct][m]
        const float4* src = (const float4*)g_Xf
                          + ((size_t)(ct0 + chunk) * NMODE + m0) * 4;
        #pragma unroll
        for (int r = 0; r < 8; r++) {
            int i   = threadIdx.x + r * 256;
            int ctl = i >> 7;           // 128 float4 per ct
            int rem = i & 127;
            int mm  = rem >> 2;         // 4 float4 per m
            int bq  = rem & 3;          // float4 bq -> batches 2bq, 2bq+1
            float4 v = src[(size_t)ctl * (NMODE * 4) + mm * 4 + bq];
            tile[2 * bq][ctl][mm]     = make_float2(v.x, v.y);
            tile[2 * bq + 1][ctl][mm] = make_float2(v.z, v.w);
        }
        __syncthreads();

        #pragma unroll 4
        for (int ctl = 0; ctl < 16; ctl++) {
            int ct = ct0 + chunk + ctl;
            float wre = reA[ct * NMODE] - reB[(size_t)ct * (128 * NMODE)];
            float wim = imA[ct * NMODE] + imB[(size_t)ct * (128 * NMODE)];
            #pragma unroll
            for (int b = 0; b < 8; b++) {
                float2 x = tile[b][ctl][mi];
                yr[b] = fmaf(wre, x.x, fmaf(-wim, x.y, yr[b]));
                yi[b] = fmaf(wre, x.y, fmaf( wim, x.x, yi[b]));
            }
        }
    }
    float2* outY = blockIdx.z ? g_Y2 : g_Y;
    #pragma unroll
    for (int b = 0; b < 8; b++)
        outY[(size_t)(b * 128 + c) * NMODE + m] = make_float2(yr[b], yi[b]);
}

// ===========================================================================
// Fused inverse per (b,c) slice. 320 threads.
// Phase A (kx->h, folded, rotation trig): P/M built from g_Y + g_Y2;
//   Z[h]=(C1-S2, C2+S1), Z[128-h]=(C1+S2, C2-S1)  -> Zev/Zod (ky parity-split)
// Phase B (ky->w c2r, QUARTER-folded, 256 threads): thread (h, w<=31) emits
//   out[w], out[128-w], out[64-w], out[64+w]; w=0 thread also emits 32/96.
// ===========================================================================
__global__ __launch_bounds__(320) void k_inv(float* __restrict__ out) {
    __shared__ float2 tb[128];
    __shared__ float2 Pa[17 * NKY];
    __shared__ float2 Ma[17 * NKY];
    __shared__ float2 Zev[128][10];     // even ky j=0..8 (pad 10 -> 80B rows)
    __shared__ float2 Zod[128][8];      // odd  ky j=0..7

    const int tid = threadIdx.x;
    if (tid < 128) {
        float s, c;
        sincospif((float)tid * (2.0f / 128.0f), &s, &c);
        tb[tid] = make_float2(c, s);
    }

    const float2* Yp  = g_Y  + (size_t)blockIdx.x * NMODE;
    const float2* Yp2 = g_Y2 + (size_t)blockIdx.x * NMODE;
    if (tid < 17 * NKY) {
        int a = tid / NKY, ky = tid - a * NKY;
        float2 ya = Yp[a * NKY + ky], yb = Yp2[a * NKY + ky];
        float2 yp = make_float2(ya.x + yb.x, ya.y + yb.y);
        float2 P, M;
        if (a == 0)       { P = yp; M = make_float2(0.f, 0.f); }
        else if (a == 16) { P = yp; M = yp; }
        else {
            float2 na = Yp[(32 - a) * NKY + ky], nb = Yp2[(32 - a) * NKY + ky];
            float2 yn = make_float2(na.x + nb.x, na.y + nb.y);
            P = make_float2(yp.x + yn.x, yp.y + yn.y);
            M = make_float2(yp.x - yn.x, yp.y - yn.y);
        }
        Pa[tid] = P;
        Ma[tid] = M;
    }
    __syncthreads();

    // Phase A
    if (tid < 272) {
        const int ky = tid % NKY;
        const int hb = tid / NKY;           // 0..15
        const int kj = ky >> 1;
        const bool odd = (ky & 1);
        float cw[4], sw[4], tc[4], ts[4];
        float C1[4], C2[4], S1[4], S2[4];
        #pragma unroll
        for (int j = 0; j < 4; j++) {
            int h = hb + 16 * j;
            sincospif((float)h * (1.0f / 64.0f), &sw[j], &cw[j]);
            tc[j] = 1.f; ts[j] = 0.f;
            C1[j] = 0.f; C2[j] = 0.f; S1[j] = 0.f; S2[j] = 0.f;
        }
        #pragma unroll
        for (int a = 0; a < NKY; a++) {
            float2 P = Pa[a * NKY + ky];
            float2 M = Ma[a * NKY + ky];
            #pragma unroll
            for (int j = 0; j < 4; j++) {
                C1[j] = fmaf(tc[j], P.x, C1[j]);
                C2[j] = fmaf(tc[j], P.y, C2[j]);
                S1[j] = fmaf(ts[j], M.x, S1[j]);
                S2[j] = fmaf(ts[j], M.y, S2[j]);
                float nc = fmaf(tc[j], cw[j], -ts[j] * sw[j]);
                ts[j] = fmaf(tc[j], sw[j],  ts[j] * cw[j]);
                tc[j] = nc;
            }
        }
        #pragma unroll
        for (int j = 0; j < 4; j++) {
            int h = hb + 16 * j;
            float2 zf = make_float2(C1[j] - S2[j], C2[j] + S1[j]);
            float2 zm = make_float2(C1[j] + S2[j], C2[j] - S1[j]);
            if (odd) {
                Zod[h][kj] = zf;
                if (h >= 1) Zod[128 - h][kj] = zm;
            } else {
                Zev[h][kj] = zf;
                if (h >= 1) Zev[128 - h][kj] = zm;
            }
        }
    } else if (tid < 289) {
        const int ky = tid - 272;           // h = 64: cos(pi a)=(-1)^a, sin=0
        float C1 = 0.f, C2 = 0.f;
        #pragma unroll
        for (int a = 0; a < NKY; a++) {
            float2 P = Pa[a * NKY + ky];
            float sg = (a & 1) ? -1.f : 1.f;
            C1 = fmaf(sg, P.x, C1);
            C2 = fmaf(sg, P.y, C2);
        }
        if (ky & 1) Zod[64][ky >> 1] = make_float2(C1, C2);
        else        Zev[64][ky >> 1] = make_float2(C1, C2);
    }
    __syncthreads();

    // Phase B
    if (tid < 256) {
        const int w  = tid & 31;
        const int h0 = (tid >> 5) * 16;
        float ck[NKY], sk[NKY];
        #pragma unroll
        for (int ky = 0; ky < NKY; ky++) {
            float2 t = tb[(ky * w) & 127];
            float a = ky ? 2.0f : 1.0f;
            ck[ky] = a * t.x;
            sk[ky] = a * t.y;
        }

        float* op = out + (size_t)blockIdx.x * 16384;
        for (int h = h0; h < h0 + 16; h++) {
            float4 e01 = *(const float4*)&Zev[h][0];
            float4 e23 = *(const float4*)&Zev[h][2];
            float4 e45 = *(const float4*)&Zev[h][4];
            float4 e67 = *(const float4*)&Zev[h][6];
            float2 e8  = Zev[h][8];
            float4 o01 = *(const float4*)&Zod[h][0];
            float4 o23 = *(const float4*)&Zod[h][2];
            float4 o45 = *(const float4*)&Zod[h][4];
            float4 o67 = *(const float4*)&Zod[h][6];

            float Ce = ck[0] * e01.x;          float Se = sk[0] * e01.y;
            Ce = fmaf(ck[2],  e01.z, Ce);      Se = fmaf(sk[2],  e01.w, Se);
            Ce = fmaf(ck[4],  e23.x, Ce);      Se = fmaf(sk[4],  e23.y, Se);
            Ce = fmaf(ck[6],  e23.z, Ce);      Se = fmaf(sk[6],  e23.w, Se);
            Ce = fmaf(ck[8],  e45.x, Ce);      Se = fmaf(sk[8],  e45.y, Se);
            Ce = fmaf(ck[10], e45.z, Ce);      Se = fmaf(sk[10], e45.w, Se);
            Ce = fmaf(ck[12], e67.x, Ce);      Se = fmaf(sk[12], e67.y, Se);
            Ce = fmaf(ck[14], e67.z, Ce);      Se = fmaf(sk[14], e67.w, Se);
            Ce = fmaf(ck[16], e8.x,  Ce);      Se = fmaf(sk[16], e8.y,  Se);

            float Co = ck[1] * o01.x;          float So = sk[1] * o01.y;
            Co = fmaf(ck[3],  o01.z, Co);      So = fmaf(sk[3],  o01.w, So);
            Co = fmaf(ck[5],  o23.x, Co);      So = fmaf(sk[5],  o23.y, So);
            Co = fmaf(ck[7],  o23.z, Co);      So = fmaf(sk[7],  o23.w, So);
            Co = fmaf(ck[9],  o45.x, Co);      So = fmaf(sk[9],  o45.y, So);
            Co = fmaf(ck[11], o45.z, Co);      So = fmaf(sk[11], o45.w, So);
            Co = fmaf(ck[13], o67.x, Co);      So = fmaf(sk[13], o67.y, So);
            Co = fmaf(ck[15], o67.z, Co);      So = fmaf(sk[15], o67.w, So);

            float Cp = Ce + Co, Cm = Ce - Co;
            float Sp = Se + So, Sm = Se - So;
            float* oph = op + h * 128;
            oph[w] = Cp - Sp;
            if (w) {
                oph[128 - w] = Cp + Sp;
                oph[64 - w]  = Cm + Sm;
                oph[64 + w]  = Cm - Sm;
            } else {
                oph[64] = Cm;
                // w = 32 / 96 (self-paired under w<->64-w):
                float C32 = e01.x;
                C32 = fmaf(-2.f, e01.z, C32);
                C32 = fmaf( 2.f, e23.x, C32);
                C32 = fmaf(-2.f, e23.z, C32);
                C32 = fmaf( 2.f, e45.x, C32);
                C32 = fmaf(-2.f, e45.z, C32);
                C32 = fmaf( 2.f, e67.x, C32);
                C32 = fmaf(-2.f, e67.z, C32);
                C32 = fmaf( 2.f, e8.x,  C32);
                float S32 = o01.y - o01.w + o23.y - o23.w
                          + o45.y - o45.w + o67.y - o67.w;
                S32 *= 2.f;
                oph[32] = C32 - S32;
                oph[96] = C32 + S32;
            }
        }
    }
}

extern "C" void kernel_launch(void* const* d_in, const int* in_sizes, int n_in,
                              void* d_out, int out_size) {
    const float* X  = (const float*)d_in[0];
    const float* re = (const float*)d_in[1];
    const float* im = (const float*)d_in[2];
    float* out = (float*)d_out;

    const int smem_fwd = 64 * 16 + (32 * 10 + 32 * 8 + 128 * NKY) * 8
                       + 2 * (64 * 33) * 8;   // 56832 B
    cudaFuncSetAttribute(k_fwd, cudaFuncAttributeMaxDynamicSharedMemorySize, smem_fwd);

    k_fwd<<<NSLICE, 320, smem_fwd>>>(X);
    k_mix<<<dim3(17, 16, 2), 256>>>(re, im);
    k_inv<<<NSLICE, 320>>>(out);
}